// round 15
// baseline (speedup 1.0000x reference)
#include <cuda_runtime.h>
#include <cuda_bf16.h>
#include <math.h>
#include <stdint.h>

typedef __nv_bfloat16 bf16;

static constexpr int Bc  = 8;
static constexpr int Sc  = 512;
static constexpr int Dc  = 512;
static constexpr int DKc = 64;
static constexpr int FFc = 2048;
static constexpr int Vc  = 10000;
static constexpr int Lc  = 6;
static constexpr int BSc = Bc * Sc;   // 4096

// ---------------- weight offsets (transposed bf16 [N,K] layout) --------------
static constexpr long long OFF_QKVO_E = 0;
static constexpr long long OFF_SA     = 24LL * 262144;
static constexpr long long OFF_CA     = 48LL * 262144;
static constexpr long long OFF_FF1E   = 72LL * 262144;
static constexpr long long OFF_FF1D   = OFF_FF1E + 6LL * 1048576;
static constexpr long long OFF_FF2E   = OFF_FF1D + 6LL * 1048576;
static constexpr long long OFF_FF2D   = OFF_FF2E + 6LL * 1048576;
static constexpr long long OFF_OUT    = OFF_FF2D + 6LL * 1048576;
static constexpr long long W_TOTAL    = OFF_OUT + 512LL * 10000;

// ---------------- scratch ----------------------------------------------------
__device__ float g_x [BSc * Dc];
__device__ float g_y [BSc * Dc];
__device__ float g_a [BSc * Dc];

__device__ bf16 g_wh[W_TOTAL];
__device__ bf16 g_wl[W_TOTAL];
__device__ bf16 g_qkvh[(size_t)BSc * 1536], g_qkvl[(size_t)BSc * 1536];
__device__ bf16 g_ah [BSc * Dc],  g_al [BSc * Dc];
__device__ bf16 g_dyh[BSc * Dc],  g_dyl[BSc * Dc];    // decoder embed split
__device__ bf16 g_fh [BSc * FFc], g_fl [BSc * FFc];
__device__ bf16 g_vth[BSc * Dc],  g_vtl[BSc * Dc];    // V^T per head [bh][64][512]
__device__ bf16 g_th [BSc * Dc],  g_tl [BSc * Dc];
__device__ bf16 g_xeh[BSc * Dc],  g_xel[BSc * Dc];

// ---------------- PTX helpers ------------------------------------------------
__device__ __forceinline__ uint32_t smem_u32(const void* p) {
    uint32_t a;
    asm("{ .reg .u64 t; cvta.to.shared.u64 t, %1; cvt.u32.u64 %0, t; }"
        : "=r"(a) : "l"(p));
    return a;
}
__device__ __forceinline__ void cpasync16(uint32_t dst, const void* src, int sz) {
    asm volatile("cp.async.cg.shared.global [%0], [%1], 16, %2;\n"
                 :: "r"(dst), "l"(src), "r"(sz));
}
#define CP_COMMIT() asm volatile("cp.async.commit_group;\n" ::: "memory")
#define CP_WAIT(n)  asm volatile("cp.async.wait_group %0;\n" :: "n"(n) : "memory")

__device__ __forceinline__ void ldm4(uint32_t* r, uint32_t addr) {
    asm volatile("ldmatrix.sync.aligned.m8n8.x4.shared.b16 {%0,%1,%2,%3}, [%4];"
                 : "=r"(r[0]), "=r"(r[1]), "=r"(r[2]), "=r"(r[3]) : "r"(addr));
}
__device__ __forceinline__ void mma_bf16(float* c, const uint32_t* a, const uint32_t* b) {
    asm volatile(
        "mma.sync.aligned.m16n8k16.row.col.f32.bf16.bf16.f32 "
        "{%0,%1,%2,%3}, {%4,%5,%6,%7}, {%8,%9}, {%0,%1,%2,%3};"
        : "+f"(c[0]), "+f"(c[1]), "+f"(c[2]), "+f"(c[3])
        : "r"(a[0]), "r"(a[1]), "r"(a[2]), "r"(a[3]), "r"(b[0]), "r"(b[1]));
}
__device__ __forceinline__ uint32_t packbf(bf16 x, bf16 y) {
    uint16_t ux = *reinterpret_cast<uint16_t*>(&x);
    uint16_t uy = *reinterpret_cast<uint16_t*>(&y);
    return (uint32_t)ux | ((uint32_t)uy << 16);
}
__device__ __forceinline__ void packsplit(float x, float y, uint32_t& hi, uint32_t& lo) {
    bf16 xh = __float2bfloat16(x);
    bf16 yh = __float2bfloat16(y);
    bf16 xl = __float2bfloat16(x - __bfloat162float(xh));
    bf16 yl = __float2bfloat16(y - __bfloat162float(yh));
    hi = packbf(xh, yh);
    lo = packbf(xl, yl);
}

// ---------------- split-bf16 HMMA GEMM (BK=32, 3-stage) ----------------------
// NT=64: 256 thr, 8 warps (4m x 2n), warp tile 32x32, 2 CTAs/SM.
template <int NT>
__global__ __launch_bounds__(NT == 128 ? 512 : 256, NT == 128 ? 1 : 2) void k_tgemm(
    const bf16* __restrict__ Ah, const bf16* __restrict__ Al, int lda,
    long long sAb, long long sAh,
    const bf16* __restrict__ Bh, const bf16* __restrict__ Bl, int ldb,
    long long sBb, long long sBh,
    float* __restrict__ C, bf16* __restrict__ Oh, bf16* __restrict__ Ol,
    int ldc, long long sCb, long long sCh,
    const float* __restrict__ bias, int relu, int N, int K, float scale)
{
    constexpr int NTH   = (NT == 128) ? 512 : 256;
    constexpr int ATILE = 128 * 80;
    constexpr int BTILE = NT * 80;
    constexpr int S_AH = 0, S_AL = ATILE, S_BH = 2 * ATILE, S_BL = 2 * ATILE + BTILE;
    constexpr int STAGE = 2 * ATILE + 2 * BTILE;

    extern __shared__ char smem[];
    const uint32_t sb = smem_u32(smem);
    const int tid = threadIdx.x, lane = tid & 31, wid = tid >> 5;
    const int wm = wid & 3, wn = wid >> 2;
    const int z = blockIdx.z, b = z >> 3, h = z & 7;
    const int m0 = blockIdx.y * 128, n0 = blockIdx.x * NT;

    const bf16* pAh = Ah + (long long)b * sAb + (long long)h * sAh;
    const bf16* pAl = Al + (long long)b * sAb + (long long)h * sAh;
    const bf16* pBh = Bh + (long long)b * sBb + (long long)h * sBh;
    const bf16* pBl = Bl + (long long)b * sBb + (long long)h * sBh;

    auto load = [&](int c, int s) {
        const int k0 = c * 32;
        const uint32_t base = sb + s * STAGE;
        for (int i = tid; i < 128 * 4; i += NTH) {
            int r = i >> 2, sub = i & 3;
            long long off = (long long)(m0 + r) * lda + k0 + sub * 8;
            uint32_t d = base + r * 80 + sub * 16;
            cpasync16(d + S_AH, pAh + off, 16);
            cpasync16(d + S_AL, pAl + off, 16);
        }
        for (int i = tid; i < NT * 4; i += NTH) {
            int r = i >> 2, sub = i & 3;
            int n = n0 + r;
            int sz = (n < N) ? 16 : 0;
            int nc = (n < N) ? n : 0;
            long long off = (long long)nc * ldb + k0 + sub * 8;
            uint32_t d = base + r * 80 + sub * 16;
            cpasync16(d + S_BH, pBh + off, sz);
            cpasync16(d + S_BL, pBl + off, sz);
        }
        CP_COMMIT();
    };

    float acc[2][4][4];
#pragma unroll
    for (int mt = 0; mt < 2; mt++)
#pragma unroll
        for (int nt = 0; nt < 4; nt++)
#pragma unroll
            for (int j = 0; j < 4; j++) acc[mt][nt][j] = 0.f;

    const int a_row = wm * 32 + (lane & 15);
    const int a_k   = ((lane >> 4) & 1) * 16;
    const int b_row = wn * 32 + (lane & 7) + ((lane >> 4) & 1) * 8;
    const int b_k   = ((lane >> 3) & 1) * 16;

    const int nch = K >> 5;
    load(0, 0);
    if (nch > 1) load(1, 1);

    for (int c = 0; c < nch; c++) {
        const int s = c % 3;
        if (c + 2 < nch) { load(c + 2, (c + 2) % 3); CP_WAIT(2); }
        else if (c + 1 < nch) CP_WAIT(1);
        else CP_WAIT(0);
        __syncthreads();
        const uint32_t st = sb + s * STAGE;
#pragma unroll
        for (int ks = 0; ks < 2; ks++) {
            uint32_t afh[2][4], afl[2][4], bfh[4][2], bfl[4][2];
#pragma unroll
            for (int mt = 0; mt < 2; mt++) {
                uint32_t ad = st + (a_row + mt * 16) * 80 + ks * 32 + a_k;
                ldm4(afh[mt], ad + S_AH);
                ldm4(afl[mt], ad + S_AL);
            }
#pragma unroll
            for (int np = 0; np < 2; np++) {
                uint32_t bd = st + (b_row + np * 16) * 80 + ks * 32 + b_k;
                uint32_t r[4];
                ldm4(r, bd + S_BH);
                bfh[np * 2][0] = r[0]; bfh[np * 2][1] = r[1];
                bfh[np * 2 + 1][0] = r[2]; bfh[np * 2 + 1][1] = r[3];
                ldm4(r, bd + S_BL);
                bfl[np * 2][0] = r[0]; bfl[np * 2][1] = r[1];
                bfl[np * 2 + 1][0] = r[2]; bfl[np * 2 + 1][1] = r[3];
            }
#pragma unroll
            for (int mt = 0; mt < 2; mt++)
#pragma unroll
                for (int nt = 0; nt < 4; nt++) {
                    mma_bf16(acc[mt][nt], afh[mt], bfh[nt]);
                    mma_bf16(acc[mt][nt], afh[mt], bfl[nt]);
                    mma_bf16(acc[mt][nt], afl[mt], bfh[nt]);
                }
        }
        __syncthreads();
    }

    const int l4 = lane >> 2, l2 = (lane & 3) * 2;
    const long long coff = (long long)b * sCb + (long long)h * sCh;
#pragma unroll
    for (int mt = 0; mt < 2; mt++) {
#pragma unroll
        for (int h2 = 0; h2 < 2; h2++) {
            const int row = m0 + wm * 32 + mt * 16 + h2 * 8 + l4;
#pragma unroll
            for (int nt = 0; nt < 4; nt++) {
#pragma unroll
                for (int j = 0; j < 2; j++) {
                    int col = n0 + wn * 32 + nt * 8 + l2 + j;
                    if (col < N) {
                        float v = acc[mt][nt][h2 * 2 + j] * scale;
                        if (bias) v += bias[col];
                        if (relu) v = fmaxf(v, 0.f);
                        long long o = coff + (long long)row * ldc + col;
                        if (C) C[o] = v;
                        if (Oh) {
                            bf16 hi = __float2bfloat16(v);
                            Oh[o] = hi;
                            Ol[o] = __float2bfloat16(v - __bfloat162float(hi));
                        }
                    }
                }
            }
        }
    }
}

// ---------------- fused flash attention (R6 datapath, unchanged) -------------
__global__ __launch_bounds__(256, 2) void k_flash(
    const bf16* __restrict__ Qh, const bf16* __restrict__ Ql,
    const bf16* __restrict__ Kh, const bf16* __restrict__ Kl,
    const bf16* __restrict__ Vth, const bf16* __restrict__ Vtl,
    bf16* __restrict__ Oh, bf16* __restrict__ Ol,
    const int* __restrict__ keytok, int causal)
{
    extern __shared__ char smem[];
    const uint32_t sb = smem_u32(smem);
    const int tid = threadIdx.x, lane = tid & 31, wid = tid >> 5;
    const int z = blockIdx.y, b = z >> 3, h = z & 7;
    const int q0 = blockIdx.x * 128;
    const int wrow = wid * 16;
    const uint32_t QLO = sb + 81920;
    float* msk = (float*)(smem + 102400);

    for (int i = tid; i < 128 * 8; i += 256) {
        int r = i >> 3, c = i & 7;
        long long off = ((long long)(b * 512 + q0 + r)) * 1536 + h * 64 + c * 8;
        uint32_t d = (uint32_t)((c >> 2) * 10240 + r * 80 + (c & 3) * 16);
        cpasync16(sb + d, Qh + off, 16);
        cpasync16(QLO + d, Ql + off, 16);
    }
    CP_COMMIT();
    for (int i = tid; i < 512; i += 256)
        msk[i] = (keytok && keytok[b * 512 + i] == 0) ? -1e30f : 0.f;
    CP_WAIT(0);
    __syncthreads();

    const int a_row = lane & 15;
    const int a_k   = ((lane >> 4) & 1) * 16;
    uint32_t qfh[4][4];
#pragma unroll
    for (int kk = 0; kk < 4; kk++)
        ldm4(qfh[kk], sb + (kk >> 1) * 10240 + (wrow + a_row) * 80 + (kk & 1) * 32 + a_k);
    __syncthreads();

    auto load = [&](int c, int s) {
        const uint32_t rb = sb + s * 40960;
        const int sk0 = c * 64;
        for (int i = tid; i < 64 * 8; i += 256) {
            int r = i >> 3, cc = i & 7;
            uint32_t d = (uint32_t)((cc >> 2) * 5120 + r * 80 + (cc & 3) * 16);
            long long ko = ((long long)(b * 512 + sk0 + r)) * 1536 + h * 64 + cc * 8;
            cpasync16(rb + d,         Kh + ko, 16);
            cpasync16(rb + 10240 + d, Kl + ko, 16);
            long long vo = ((long long)(z * 64 + r)) * 512 + sk0 + cc * 8;
            cpasync16(rb + 20480 + d, Vth + vo, 16);
            cpasync16(rb + 30720 + d, Vtl + vo, 16);
        }
        CP_COMMIT();
    };

    const int b_row = (lane & 7) + ((lane >> 4) & 1) * 8;
    const int b_k   = ((lane >> 3) & 1) * 16;

    float oacc[8][4];
#pragma unroll
    for (int nt = 0; nt < 8; nt++)
#pragma unroll
        for (int e = 0; e < 4; e++) oacc[nt][e] = 0.f;
    float m_r[2] = {-1e30f, -1e30f};
    float l_r[2] = {0.f, 0.f};

    const int nch = causal ? ((q0 >> 6) + 2) : 8;
    load(0, 0);

    for (int c = 0; c < nch; c++) {
        const int s = c & 1;
        if (c + 1 < nch) { load(c + 1, s ^ 1); CP_WAIT(1); }
        else CP_WAIT(0);
        __syncthreads();
        const uint32_t rb = sb + s * 40960;

        float sacc[8][4];
#pragma unroll
        for (int nt = 0; nt < 8; nt++)
#pragma unroll
            for (int e = 0; e < 4; e++) sacc[nt][e] = 0.f;
#pragma unroll
        for (int kk = 0; kk < 4; kk++) {
            uint32_t ql4[4];
            ldm4(ql4, QLO + (kk >> 1) * 10240 + (wrow + a_row) * 80 + (kk & 1) * 32 + a_k);
#pragma unroll
            for (int np = 0; np < 4; np++) {
                uint32_t rh[4], rl[4];
                uint32_t bd = rb + (kk >> 1) * 5120 + (b_row + np * 16) * 80
                            + (kk & 1) * 32 + b_k;
                ldm4(rh, bd);
                ldm4(rl, bd + 10240);
                uint32_t bh0[2] = {rh[0], rh[1]}, bh1[2] = {rh[2], rh[3]};
                uint32_t bl0[2] = {rl[0], rl[1]}, bl1[2] = {rl[2], rl[3]};
                mma_bf16(sacc[2 * np],     qfh[kk], bh0);
                mma_bf16(sacc[2 * np],     qfh[kk], bl0);
                mma_bf16(sacc[2 * np],     ql4,     bh0);
                mma_bf16(sacc[2 * np + 1], qfh[kk], bh1);
                mma_bf16(sacc[2 * np + 1], qfh[kk], bl1);
                mma_bf16(sacc[2 * np + 1], ql4,     bh1);
            }
        }

        const int sk0 = c * 64;
        const int row0 = q0 + wrow + (lane >> 2);
        const int colb = (lane & 3) * 2;
#pragma unroll
        for (int nt = 0; nt < 8; nt++)
#pragma unroll
            for (int e = 0; e < 4; e++) {
                int col = sk0 + nt * 8 + colb + (e & 1);
                int row = row0 + (e >> 1) * 8;
                float v = sacc[nt][e] * 0.125f + msk[col];
                if (causal && col > row) v = -1e30f;
                sacc[nt][e] = v;
            }

        float mx[2] = {-1e30f, -1e30f};
#pragma unroll
        for (int nt = 0; nt < 8; nt++)
#pragma unroll
            for (int e = 0; e < 4; e++)
                mx[e >> 1] = fmaxf(mx[e >> 1], sacc[nt][e]);
#pragma unroll
        for (int r = 0; r < 2; r++) {
            mx[r] = fmaxf(mx[r], __shfl_xor_sync(0xffffffffu, mx[r], 1));
            mx[r] = fmaxf(mx[r], __shfl_xor_sync(0xffffffffu, mx[r], 2));
        }
        float corr[2], mnew[2];
#pragma unroll
        for (int r = 0; r < 2; r++) {
            mnew[r] = fmaxf(m_r[r], mx[r]);
            corr[r] = __expf(m_r[r] - mnew[r]);
            m_r[r] = mnew[r];
        }
        float sum[2] = {0.f, 0.f};
#pragma unroll
        for (int nt = 0; nt < 8; nt++)
#pragma unroll
            for (int e = 0; e < 4; e++) {
                float p = __expf(sacc[nt][e] - mnew[e >> 1]);
                sacc[nt][e] = p;
                sum[e >> 1] += p;
            }
#pragma unroll
        for (int r = 0; r < 2; r++) {
            sum[r] += __shfl_xor_sync(0xffffffffu, sum[r], 1);
            sum[r] += __shfl_xor_sync(0xffffffffu, sum[r], 2);
            l_r[r] = l_r[r] * corr[r] + sum[r];
        }
#pragma unroll
        for (int nt = 0; nt < 8; nt++)
#pragma unroll
            for (int e = 0; e < 4; e++) oacc[nt][e] *= corr[e >> 1];

#pragma unroll
        for (int g = 0; g < 4; g++) {
            uint32_t pah[4], pal[4];
            packsplit(sacc[2 * g][0],     sacc[2 * g][1],     pah[0], pal[0]);
            packsplit(sacc[2 * g][2],     sacc[2 * g][3],     pah[1], pal[1]);
            packsplit(sacc[2 * g + 1][0], sacc[2 * g + 1][1], pah[2], pal[2]);
            packsplit(sacc[2 * g + 1][2], sacc[2 * g + 1][3], pah[3], pal[3]);
#pragma unroll
            for (int np = 0; np < 4; np++) {
                uint32_t rh[4], rl[4];
                uint32_t vd = rb + 20480 + (g >> 1) * 5120 + (b_row + np * 16) * 80
                            + (g & 1) * 32 + b_k;
                ldm4(rh, vd);
                ldm4(rl, vd + 10240);
                uint32_t bh0[2] = {rh[0], rh[1]}, bh1[2] = {rh[2], rh[3]};
                uint32_t bl0[2] = {rl[0], rl[1]}, bl1[2] = {rl[2], rl[3]};
                mma_bf16(oacc[2 * np],     pah, bh0);
                mma_bf16(oacc[2 * np],     pah, bl0);
                mma_bf16(oacc[2 * np],     pal, bh0);
                mma_bf16(oacc[2 * np + 1], pah, bh1);
                mma_bf16(oacc[2 * np + 1], pah, bl1);
                mma_bf16(oacc[2 * np + 1], pal, bh1);
            }
        }
        __syncthreads();
    }

#pragma unroll
    for (int r = 0; r < 2; r++) {
        float inv = 1.f / l_r[r];
        int row = q0 + wrow + (lane >> 2) + r * 8;
        long long base = ((long long)(b * 512 + row)) * 512 + h * 64 + (lane & 3) * 2;
#pragma unroll
        for (int nt = 0; nt < 8; nt++) {
            float v0 = oacc[nt][r * 2 + 0] * inv;
            float v1 = oacc[nt][r * 2 + 1] * inv;
            bf16 h0 = __float2bfloat16(v0);
            bf16 h1 = __float2bfloat16(v1);
            uint32_t hi = packbf(h0, h1);
            uint32_t lo = packbf(__float2bfloat16(v0 - __bfloat162float(h0)),
                                 __float2bfloat16(v1 - __bfloat162float(h1)));
            *reinterpret_cast<uint32_t*>(Oh + base + nt * 8) = hi;
            *reinterpret_cast<uint32_t*>(Ol + base + nt * 8) = lo;
        }
    }
}

// ---------------- merged weight transpose+split (3 sources, contiguous out) --
__global__ void k_tsplitw(const float* __restrict__ inA, const float* __restrict__ inB,
                          const float* __restrict__ inC, bf16* __restrict__ oh,
                          bf16* __restrict__ ol, int K, int N, int per)
{
    __shared__ float t[32][33];
    const int z = blockIdx.z;
    const float* in = (z < per) ? inA : ((z < 2 * per) ? inB : inC);
    const int zz = z % per;
    const long long ib = (long long)zz * K * N;
    const long long ob = (long long)z * K * N;
    const int n0 = blockIdx.x * 32, k0 = blockIdx.y * 32;
    const int tx = threadIdx.x, ty = threadIdx.y;

    for (int r = ty; r < 32; r += 8) {
        int k = k0 + r, n = n0 + tx;
        t[r][tx] = (k < K && n < N) ? in[ib + (long long)k * N + n] : 0.f;
    }
    __syncthreads();
    for (int r = ty; r < 32; r += 8) {
        int n = n0 + r, k = k0 + tx;
        if (n < N && k < K) {
            float x = t[tx][r];
            bf16 hi = __float2bfloat16(x);
            oh[ob + (long long)n * K + k] = hi;
            ol[ob + (long long)n * K + k] = __float2bfloat16(x - __bfloat162float(hi));
        }
    }
}

// ---------------- V^T split from qkv bf16 buffer ------------------------------
__global__ void k_vtsplit(const bf16* __restrict__ ih, const bf16* __restrict__ il,
                          bf16* __restrict__ oh, bf16* __restrict__ ol)
{
    __shared__ float t[32][33];
    const int z = blockIdx.z, b = z >> 3, h = z & 7;
    const int n0 = blockIdx.x * 32, s0 = blockIdx.y * 32;
    const int tx = threadIdx.x, ty = threadIdx.y;
    const long long ib = (long long)b * 512 * 1536 + 1024 + h * 64;
    const long long ob = (long long)z * 64 * 512;

    for (int r = ty; r < 32; r += 8) {
        long long off = ib + (long long)(s0 + r) * 1536 + n0 + tx;
        t[r][tx] = __bfloat162float(ih[off]) + __bfloat162float(il[off]);
    }
    __syncthreads();
    for (int r = ty; r < 32; r += 8) {
        float x = t[tx][r];
        bf16 hi = __float2bfloat16(x);
        long long o = ob + (long long)(n0 + r) * 512 + s0 + tx;
        oh[o] = hi;
        ol[o] = __float2bfloat16(x - __bfloat162float(hi));
    }
}

// ---------------- embedding + posenc (+ split) -------------------------------
__global__ void k_embed(const int* __restrict__ tok, const float* __restrict__ emb,
                        float* __restrict__ out, bf16* __restrict__ oh,
                        bf16* __restrict__ ol)
{
    int idx = blockIdx.x * blockDim.x + threadIdx.x;
    if (idx >= BSc * Dc) return;
    int d  = idx & (Dc - 1);
    int bs = idx >> 9;
    int s  = bs & (Sc - 1);
    int t  = tok[bs];
    int i2 = d & ~1;
    float div = expf((float)i2 * (-9.210340371976184f / (float)Dc));
    float ang = (float)s * div;
    float pe  = (d & 1) ? cosf(ang) : sinf(ang);
    float v = emb[(size_t)t * Dc + d] + pe;
    out[idx] = v;
    bf16 hi = __float2bfloat16(v);
    oh[idx] = hi;
    ol[idx] = __float2bfloat16(v - __bfloat162float(hi));
}

// ---------------- residual + LayerNorm (+ split out) -------------------------
__global__ __launch_bounds__(256) void k_lnres(
    const float* __restrict__ X, const float* __restrict__ Dl,
    const float* __restrict__ g, const float* __restrict__ bt,
    float* __restrict__ Out, bf16* __restrict__ oh, bf16* __restrict__ ol)
{
    int warp = threadIdx.x >> 5, lane = threadIdx.x & 31;
    size_t row = (size_t)blockIdx.x * 8 + warp;
    const float* px = X  + row * Dc;
    const float* pd = Dl + row * Dc;
    float v[16];
    float s = 0.f;
#pragma unroll
    for (int i = 0; i < 16; i++) { v[i] = px[lane + i * 32] + pd[lane + i * 32]; s += v[i]; }
#pragma unroll
    for (int o = 16; o; o >>= 1) s += __shfl_xor_sync(0xffffffffu, s, o);
    float mu = s * (1.f / (float)Dc);
    float var = 0.f;
#pragma unroll
    for (int i = 0; i < 16; i++) { float d = v[i] - mu; var += d * d; }
#pragma unroll
    for (int o = 16; o; o >>= 1) var += __shfl_xor_sync(0xffffffffu, var, o);
    var *= (1.f / (float)Dc);
    float inv = rsqrtf(var + 1e-5f);
#pragma unroll
    for (int i = 0; i < 16; i++) {
        int c = lane + i * 32;
        float o = (v[i] - mu) * inv * g[c] + bt[c];
        Out[row * Dc + c] = o;
        bf16 hi = __float2bfloat16(o);
        oh[row * Dc + c] = hi;
        ol[row * Dc + c] = __float2bfloat16(o - __bfloat162float(hi));
    }
}

// =============================================================================
extern "C" void kernel_launch(void* const* d_in, const int* in_sizes, int n_in,
                              void* d_out, int out_size)
{
    const int*   src      = (const int*)  d_in[0];
    const int*   tgt      = (const int*)  d_in[1];
    const float* src_emb  = (const float*)d_in[2];
    const float* tgt_emb  = (const float*)d_in[3];
    const float* e_qkvo_w = (const float*)d_in[4];
    const float* e_qkvo_b = (const float*)d_in[5];
    const float* e_ff1_w  = (const float*)d_in[6];
    const float* e_ff1_b  = (const float*)d_in[7];
    const float* e_ff2_w  = (const float*)d_in[8];
    const float* e_ff2_b  = (const float*)d_in[9];
    const float* e_ln_g   = (const float*)d_in[10];
    const float* e_ln_b   = (const float*)d_in[11];
    const float* d_sa_w   = (const float*)d_in[12];
    const float* d_sa_b   = (const float*)d_in[13];
    const float* d_ca_w   = (const float*)d_in[14];
    const float* d_ca_b   = (const float*)d_in[15];
    const float* d_ff1_w  = (const float*)d_in[16];
    const float* d_ff1_b  = (const float*)d_in[17];
    const float* d_ff2_w  = (const float*)d_in[18];
    const float* d_ff2_b  = (const float*)d_in[19];
    const float* d_ln_g   = (const float*)d_in[20];
    const float* d_ln_b   = (const float*)d_in[21];
    const float* out_w    = (const float*)d_in[22];
    const float* out_b    = (const float*)d_in[23];
    float* out = (float*)d_out;

    float *px, *py, *pa;
    bf16 *wh, *wl, *qvh, *qvl, *ah, *al, *dyh, *dyl, *fh, *fl, *vth, *vtl,
         *th, *tl, *xeh, *xel;
    cudaGetSymbolAddress((void**)&px,  g_x);
    cudaGetSymbolAddress((void**)&py,  g_y);
    cudaGetSymbolAddress((void**)&pa,  g_a);
    cudaGetSymbolAddress((void**)&wh,  g_wh);
    cudaGetSymbolAddress((void**)&wl,  g_wl);
    cudaGetSymbolAddress((void**)&qvh, g_qkvh);
    cudaGetSymbolAddress((void**)&qvl, g_qkvl);
    cudaGetSymbolAddress((void**)&ah,  g_ah);
    cudaGetSymbolAddress((void**)&al,  g_al);
    cudaGetSymbolAddress((void**)&dyh, g_dyh);
    cudaGetSymbolAddress((void**)&dyl, g_dyl);
    cudaGetSymbolAddress((void**)&fh,  g_fh);
    cudaGetSymbolAddress((void**)&fl,  g_fl);
    cudaGetSymbolAddress((void**)&vth, g_vth);
    cudaGetSymbolAddress((void**)&vtl, g_vtl);
    cudaGetSymbolAddress((void**)&th,  g_th);
    cudaGetSymbolAddress((void**)&tl,  g_tl);
    cudaGetSymbolAddress((void**)&xeh, g_xeh);
    cudaGetSymbolAddress((void**)&xel, g_xel);

    const int SMEM64 = 3 * (2 * 128 * 80 + 2 * 64 * 80);   // 92160 -> 2 CTAs/SM
    const int FLASH_SMEM = 104448;
    cudaFuncSetAttribute((const void*)k_tgemm<64>,
                         cudaFuncAttributeMaxDynamicSharedMemorySize, SMEM64);
    cudaFuncSetAttribute((const void*)k_flash,
                         cudaFuncAttributeMaxDynamicSharedMemorySize, FLASH_SMEM);

    // ---- launchers ----------------------------------------------------------
    auto dense = [&](const bf16* Axh, const bf16* Axl, int lda, long long woff,
                     int ldb, float* C, bf16* Oh, bf16* Ol, int ldc,
                     const float* bias, int relu, int N, int K) {
        dim3 g((N + 63) / 64, BSc / 128, 1);
        k_tgemm<64><<<g, 256, SMEM64>>>(Axh, Axl, lda, 0, 0,
                                        wh + woff, wl + woff, ldb, 0, 0,
                                        C, Oh, Ol, ldc, 0, 0,
                                        bias, relu, N, K, 1.f);
    };
    auto flash = [&](int causal, const int* kt) {
        k_flash<<<dim3(4, 64), 256, FLASH_SMEM>>>(qvh, qvl, qvh + 512, qvl + 512,
                                                  vth, vtl, th, tl, kt, causal);
    };
    auto vtsplit = [&]() {
        k_vtsplit<<<dim3(2, 16, 64), dim3(32, 8)>>>(qvh, qvl, vth, vtl);
    };
    const int ln_blocks = BSc / 8;
    const long long DD = (long long)Dc * Dc;

    // ---- prologue (launch #4 = dense GEMM, captured by ncu) ------------------
    k_tsplitw<<<dim3(16, 16, 72), dim3(32, 8)>>>(e_qkvo_w, d_sa_w, d_ca_w,
                                                 wh, wl, 512, 512, 24);
    k_embed<<<(BSc * Dc + 255) / 256, 256>>>(src, src_emb, px, ah, al);
    k_tsplitw<<<dim3(64, 16, 12), dim3(32, 8)>>>(e_ff1_w, d_ff1_w, d_ff1_w,
                                                 wh + OFF_FF1E, wl + OFF_FF1E,
                                                 512, 2048, 6);
    dense(ah, al, Dc, OFF_QKVO_E, Dc, nullptr, qvh, qvl, 1536, e_qkvo_b, 0, 1536, Dc);
    k_tsplitw<<<dim3(16, 64, 12), dim3(32, 8)>>>(e_ff2_w, d_ff2_w, d_ff2_w,
                                                 wh + OFF_FF2E, wl + OFF_FF2E,
                                                 2048, 512, 6);
    k_tsplitw<<<dim3(313, 16, 1), dim3(32, 8)>>>(out_w, out_w, out_w,
                                                 wh + OFF_OUT, wl + OFF_OUT,
                                                 512, 10000, 1);
    k_embed<<<(BSc * Dc + 255) / 256, 256>>>(tgt, tgt_emb, py, dyh, dyl);

    // ================= encoder =================
    for (int l = 0; l < Lc; l++) {
        long long w = OFF_QKVO_E + (long long)l * 4 * DD;
        const float* b = e_qkvo_b + (size_t)l * 4 * Dc;
        if (l > 0)
            dense(ah, al, Dc, w, Dc, nullptr, qvh, qvl, 1536, b, 0, 1536, Dc);
        vtsplit();
        flash(0, src);
        dense(th, tl, Dc, w + 3 * DD, Dc, pa, nullptr, nullptr, Dc, b + 3 * Dc, 0, Dc, Dc);
        k_lnres<<<ln_blocks, 256>>>(px, pa, e_ln_g + (size_t)l * 2 * Dc,
                                    e_ln_b + (size_t)l * 2 * Dc, px, ah, al);
        dense(ah, al, Dc, OFF_FF1E + (long long)l * Dc * FFc, Dc,
              nullptr, fh, fl, FFc, e_ff1_b + (size_t)l * FFc, 1, FFc, Dc);
        dense(fh, fl, FFc, OFF_FF2E + (long long)l * Dc * FFc, FFc,
              pa, nullptr, nullptr, Dc, e_ff2_b + (size_t)l * Dc, 0, Dc, FFc);
        bf16* oh2 = (l == Lc - 1) ? xeh : ah;
        bf16* ol2 = (l == Lc - 1) ? xel : al;
        k_lnres<<<ln_blocks, 256>>>(px, pa, e_ln_g + (size_t)l * 2 * Dc + Dc,
                                    e_ln_b + (size_t)l * 2 * Dc + Dc, px, oh2, ol2);
    }

    // ================= decoder =================
    for (int l = 0; l < Lc; l++) {
        long long ws = OFF_SA + (long long)l * 4 * DD;
        const float* bs = d_sa_b + (size_t)l * 4 * Dc;
        const bf16* ain_h = (l == 0) ? dyh : ah;
        const bf16* ain_l = (l == 0) ? dyl : al;
        dense(ain_h, ain_l, Dc, ws, Dc, nullptr, qvh, qvl, 1536, bs, 0, 1536, Dc);
        vtsplit();
        flash(1, nullptr);
        dense(th, tl, Dc, ws + 3 * DD, Dc, pa, nullptr, nullptr, Dc, bs + 3 * Dc, 0, Dc, Dc);
        k_lnres<<<ln_blocks, 256>>>(py, pa, d_ln_g + (size_t)l * 3 * Dc,
                                    d_ln_b + (size_t)l * 3 * Dc, py, ah, al);

        long long wc = OFF_CA + (long long)l * 4 * DD;
        const float* bc = d_ca_b + (size_t)l * 4 * Dc;
        dense(ah,  al,  Dc, wc,      Dc, nullptr, qvh, qvl, 1536, bc, 0, Dc, Dc);
        dense(xeh, xel, Dc, wc + DD, Dc, nullptr, qvh + 512, qvl + 512, 1536,
              bc + Dc, 0, 1024, Dc);
        vtsplit();
        flash(0, tgt);
        dense(th, tl, Dc, wc + 3 * DD, Dc, pa, nullptr, nullptr, Dc, bc + 3 * Dc, 0, Dc, Dc);
        k_lnres<<<ln_blocks, 256>>>(py, pa, d_ln_g + (size_t)l * 3 * Dc + Dc,
                                    d_ln_b + (size_t)l * 3 * Dc + Dc, py, ah, al);

        dense(ah, al, Dc, OFF_FF1D + (long long)l * Dc * FFc, Dc,
              nullptr, fh, fl, FFc, d_ff1_b + (size_t)l * FFc, 1, FFc, Dc);
        dense(fh, fl, FFc, OFF_FF2D + (long long)l * Dc * FFc, FFc,
              pa, nullptr, nullptr, Dc, d_ff2_b + (size_t)l * Dc, 0, Dc, FFc);
        k_lnres<<<ln_blocks, 256>>>(py, pa, d_ln_g + (size_t)l * 3 * Dc + 2 * Dc,
                                    d_ln_b + (size_t)l * 3 * Dc + 2 * Dc, py, ah, al);
    }

    // ================= output projection =================
    dense(ah, al, Dc, OFF_OUT, Dc, out, nullptr, nullptr, Vc, out_b, 0, Vc, Dc);
}

// round 16
// speedup vs baseline: 1.5267x; 1.5267x over previous
#include <cuda_runtime.h>
#include <cuda_bf16.h>
#include <math.h>
#include <stdint.h>

typedef __nv_bfloat16 bf16;

static constexpr int Bc  = 8;
static constexpr int Sc  = 512;
static constexpr int Dc  = 512;
static constexpr int DKc = 64;
static constexpr int FFc = 2048;
static constexpr int Vc  = 10000;
static constexpr int Lc  = 6;
static constexpr int BSc = Bc * Sc;   // 4096

// ---------------- weight offsets (transposed bf16 [N,K] layout) --------------
static constexpr long long OFF_QKVO_E = 0;
static constexpr long long OFF_SA     = 24LL * 262144;
static constexpr long long OFF_CA     = 48LL * 262144;
static constexpr long long OFF_FF1E   = 72LL * 262144;
static constexpr long long OFF_FF1D   = OFF_FF1E + 6LL * 1048576;
static constexpr long long OFF_FF2E   = OFF_FF1D + 6LL * 1048576;
static constexpr long long OFF_FF2D   = OFF_FF2E + 6LL * 1048576;
static constexpr long long OFF_OUT    = OFF_FF2D + 6LL * 1048576;
static constexpr long long W_TOTAL    = OFF_OUT + 512LL * 10000;

// ---------------- scratch ----------------------------------------------------
__device__ float g_x [BSc * Dc];
__device__ float g_y [BSc * Dc];
__device__ float g_a [BSc * Dc];

__device__ bf16 g_wh[W_TOTAL];
__device__ bf16 g_wl[W_TOTAL];
__device__ bf16 g_qkvh[(size_t)BSc * 1536], g_qkvl[(size_t)BSc * 1536];
__device__ bf16 g_ah [BSc * Dc],  g_al [BSc * Dc];
__device__ bf16 g_dyh[BSc * Dc],  g_dyl[BSc * Dc];    // decoder embed split
__device__ bf16 g_fh [BSc * FFc], g_fl [BSc * FFc];
__device__ bf16 g_vth[BSc * Dc],  g_vtl[BSc * Dc];    // V^T per head [bh][64][512]
__device__ bf16 g_th [BSc * Dc],  g_tl [BSc * Dc];
__device__ bf16 g_xeh[BSc * Dc],  g_xel[BSc * Dc];

// ---------------- PTX helpers ------------------------------------------------
__device__ __forceinline__ uint32_t smem_u32(const void* p) {
    uint32_t a;
    asm("{ .reg .u64 t; cvta.to.shared.u64 t, %1; cvt.u32.u64 %0, t; }"
        : "=r"(a) : "l"(p));
    return a;
}
__device__ __forceinline__ void cpasync16(uint32_t dst, const void* src, int sz) {
    asm volatile("cp.async.cg.shared.global [%0], [%1], 16, %2;\n"
                 :: "r"(dst), "l"(src), "r"(sz));
}
#define CP_COMMIT() asm volatile("cp.async.commit_group;\n" ::: "memory")
#define CP_WAIT(n)  asm volatile("cp.async.wait_group %0;\n" :: "n"(n) : "memory")

__device__ __forceinline__ void ldm4(uint32_t* r, uint32_t addr) {
    asm volatile("ldmatrix.sync.aligned.m8n8.x4.shared.b16 {%0,%1,%2,%3}, [%4];"
                 : "=r"(r[0]), "=r"(r[1]), "=r"(r[2]), "=r"(r[3]) : "r"(addr));
}
__device__ __forceinline__ void mma_bf16(float* c, const uint32_t* a, const uint32_t* b) {
    asm volatile(
        "mma.sync.aligned.m16n8k16.row.col.f32.bf16.bf16.f32 "
        "{%0,%1,%2,%3}, {%4,%5,%6,%7}, {%8,%9}, {%0,%1,%2,%3};"
        : "+f"(c[0]), "+f"(c[1]), "+f"(c[2]), "+f"(c[3])
        : "r"(a[0]), "r"(a[1]), "r"(a[2]), "r"(a[3]), "r"(b[0]), "r"(b[1]));
}
__device__ __forceinline__ uint32_t packbf(bf16 x, bf16 y) {
    uint16_t ux = *reinterpret_cast<uint16_t*>(&x);
    uint16_t uy = *reinterpret_cast<uint16_t*>(&y);
    return (uint32_t)ux | ((uint32_t)uy << 16);
}
__device__ __forceinline__ void packsplit(float x, float y, uint32_t& hi, uint32_t& lo) {
    bf16 xh = __float2bfloat16(x);
    bf16 yh = __float2bfloat16(y);
    bf16 xl = __float2bfloat16(x - __bfloat162float(xh));
    bf16 yl = __float2bfloat16(y - __bfloat162float(yh));
    hi = packbf(xh, yh);
    lo = packbf(xl, yl);
}

// ---------------- split-bf16 HMMA GEMM (BK=32, 3-stage) ----------------------
// NT=64: 256 thr, 8 warps (4m x 2n), warp tile 32x32, 2 CTAs/SM.
template <int NT>
__global__ __launch_bounds__(NT == 128 ? 512 : 256, NT == 128 ? 1 : 2) void k_tgemm(
    const bf16* __restrict__ Ah, const bf16* __restrict__ Al, int lda,
    long long sAb, long long sAh,
    const bf16* __restrict__ Bh, const bf16* __restrict__ Bl, int ldb,
    long long sBb, long long sBh,
    float* __restrict__ C, bf16* __restrict__ Oh, bf16* __restrict__ Ol,
    int ldc, long long sCb, long long sCh,
    const float* __restrict__ bias, int relu, int N, int K, float scale)
{
    constexpr int NTH   = (NT == 128) ? 512 : 256;
    constexpr int ATILE = 128 * 80;
    constexpr int BTILE = NT * 80;
    constexpr int S_AH = 0, S_AL = ATILE, S_BH = 2 * ATILE, S_BL = 2 * ATILE + BTILE;
    constexpr int STAGE = 2 * ATILE + 2 * BTILE;

    extern __shared__ char smem[];
    const uint32_t sb = smem_u32(smem);
    const int tid = threadIdx.x, lane = tid & 31, wid = tid >> 5;
    const int wm = wid & 3, wn = wid >> 2;
    const int z = blockIdx.z, b = z >> 3, h = z & 7;
    const int m0 = blockIdx.y * 128, n0 = blockIdx.x * NT;

    const bf16* pAh = Ah + (long long)b * sAb + (long long)h * sAh;
    const bf16* pAl = Al + (long long)b * sAb + (long long)h * sAh;
    const bf16* pBh = Bh + (long long)b * sBb + (long long)h * sBh;
    const bf16* pBl = Bl + (long long)b * sBb + (long long)h * sBh;

    auto load = [&](int c, int s) {
        const int k0 = c * 32;
        const uint32_t base = sb + s * STAGE;
        for (int i = tid; i < 128 * 4; i += NTH) {
            int r = i >> 2, sub = i & 3;
            long long off = (long long)(m0 + r) * lda + k0 + sub * 8;
            uint32_t d = base + r * 80 + sub * 16;
            cpasync16(d + S_AH, pAh + off, 16);
            cpasync16(d + S_AL, pAl + off, 16);
        }
        for (int i = tid; i < NT * 4; i += NTH) {
            int r = i >> 2, sub = i & 3;
            int n = n0 + r;
            int sz = (n < N) ? 16 : 0;
            int nc = (n < N) ? n : 0;
            long long off = (long long)nc * ldb + k0 + sub * 8;
            uint32_t d = base + r * 80 + sub * 16;
            cpasync16(d + S_BH, pBh + off, sz);
            cpasync16(d + S_BL, pBl + off, sz);
        }
        CP_COMMIT();
    };

    float acc[2][4][4];
#pragma unroll
    for (int mt = 0; mt < 2; mt++)
#pragma unroll
        for (int nt = 0; nt < 4; nt++)
#pragma unroll
            for (int j = 0; j < 4; j++) acc[mt][nt][j] = 0.f;

    const int a_row = wm * 32 + (lane & 15);
    const int a_k   = ((lane >> 4) & 1) * 16;
    const int b_row = wn * 32 + (lane & 7) + ((lane >> 4) & 1) * 8;
    const int b_k   = ((lane >> 3) & 1) * 16;

    const int nch = K >> 5;
    load(0, 0);
    if (nch > 1) load(1, 1);

    for (int c = 0; c < nch; c++) {
        const int s = c % 3;
        if (c + 2 < nch) { load(c + 2, (c + 2) % 3); CP_WAIT(2); }
        else if (c + 1 < nch) CP_WAIT(1);
        else CP_WAIT(0);
        __syncthreads();
        const uint32_t st = sb + s * STAGE;
#pragma unroll
        for (int ks = 0; ks < 2; ks++) {
            uint32_t afh[2][4], afl[2][4], bfh[4][2], bfl[4][2];
#pragma unroll
            for (int mt = 0; mt < 2; mt++) {
                uint32_t ad = st + (a_row + mt * 16) * 80 + ks * 32 + a_k;
                ldm4(afh[mt], ad + S_AH);
                ldm4(afl[mt], ad + S_AL);
            }
#pragma unroll
            for (int np = 0; np < 2; np++) {
                uint32_t bd = st + (b_row + np * 16) * 80 + ks * 32 + b_k;
                uint32_t r[4];
                ldm4(r, bd + S_BH);
                bfh[np * 2][0] = r[0]; bfh[np * 2][1] = r[1];
                bfh[np * 2 + 1][0] = r[2]; bfh[np * 2 + 1][1] = r[3];
                ldm4(r, bd + S_BL);
                bfl[np * 2][0] = r[0]; bfl[np * 2][1] = r[1];
                bfl[np * 2 + 1][0] = r[2]; bfl[np * 2 + 1][1] = r[3];
            }
#pragma unroll
            for (int mt = 0; mt < 2; mt++)
#pragma unroll
                for (int nt = 0; nt < 4; nt++) {
                    mma_bf16(acc[mt][nt], afh[mt], bfh[nt]);
                    mma_bf16(acc[mt][nt], afh[mt], bfl[nt]);
                    mma_bf16(acc[mt][nt], afl[mt], bfh[nt]);
                }
        }
        __syncthreads();
    }

    const int l4 = lane >> 2, l2 = (lane & 3) * 2;
    const long long coff = (long long)b * sCb + (long long)h * sCh;
#pragma unroll
    for (int mt = 0; mt < 2; mt++) {
#pragma unroll
        for (int h2 = 0; h2 < 2; h2++) {
            const int row = m0 + wm * 32 + mt * 16 + h2 * 8 + l4;
#pragma unroll
            for (int nt = 0; nt < 4; nt++) {
#pragma unroll
                for (int j = 0; j < 2; j++) {
                    int col = n0 + wn * 32 + nt * 8 + l2 + j;
                    if (col < N) {
                        float v = acc[mt][nt][h2 * 2 + j] * scale;
                        if (bias) v += bias[col];
                        if (relu) v = fmaxf(v, 0.f);
                        long long o = coff + (long long)row * ldc + col;
                        if (C) C[o] = v;
                        if (Oh) {
                            bf16 hi = __float2bfloat16(v);
                            Oh[o] = hi;
                            Ol[o] = __float2bfloat16(v - __bfloat162float(hi));
                        }
                    }
                }
            }
        }
    }
}

// ---------------- fused flash attention (R6 datapath, unchanged) -------------
__global__ __launch_bounds__(256, 2) void k_flash(
    const bf16* __restrict__ Qh, const bf16* __restrict__ Ql,
    const bf16* __restrict__ Kh, const bf16* __restrict__ Kl,
    const bf16* __restrict__ Vth, const bf16* __restrict__ Vtl,
    bf16* __restrict__ Oh, bf16* __restrict__ Ol,
    const int* __restrict__ keytok, int causal)
{
    extern __shared__ char smem[];
    const uint32_t sb = smem_u32(smem);
    const int tid = threadIdx.x, lane = tid & 31, wid = tid >> 5;
    const int z = blockIdx.y, b = z >> 3, h = z & 7;
    const int q0 = blockIdx.x * 128;
    const int wrow = wid * 16;
    const uint32_t QLO = sb + 81920;
    float* msk = (float*)(smem + 102400);

    for (int i = tid; i < 128 * 8; i += 256) {
        int r = i >> 3, c = i & 7;
        long long off = ((long long)(b * 512 + q0 + r)) * 1536 + h * 64 + c * 8;
        uint32_t d = (uint32_t)((c >> 2) * 10240 + r * 80 + (c & 3) * 16);
        cpasync16(sb + d, Qh + off, 16);
        cpasync16(QLO + d, Ql + off, 16);
    }
    CP_COMMIT();
    for (int i = tid; i < 512; i += 256)
        msk[i] = (keytok && keytok[b * 512 + i] == 0) ? -1e30f : 0.f;
    CP_WAIT(0);
    __syncthreads();

    const int a_row = lane & 15;
    const int a_k   = ((lane >> 4) & 1) * 16;
    uint32_t qfh[4][4];
#pragma unroll
    for (int kk = 0; kk < 4; kk++)
        ldm4(qfh[kk], sb + (kk >> 1) * 10240 + (wrow + a_row) * 80 + (kk & 1) * 32 + a_k);
    __syncthreads();

    auto load = [&](int c, int s) {
        const uint32_t rb = sb + s * 40960;
        const int sk0 = c * 64;
        for (int i = tid; i < 64 * 8; i += 256) {
            int r = i >> 3, cc = i & 7;
            uint32_t d = (uint32_t)((cc >> 2) * 5120 + r * 80 + (cc & 3) * 16);
            long long ko = ((long long)(b * 512 + sk0 + r)) * 1536 + h * 64 + cc * 8;
            cpasync16(rb + d,         Kh + ko, 16);
            cpasync16(rb + 10240 + d, Kl + ko, 16);
            long long vo = ((long long)(z * 64 + r)) * 512 + sk0 + cc * 8;
            cpasync16(rb + 20480 + d, Vth + vo, 16);
            cpasync16(rb + 30720 + d, Vtl + vo, 16);
        }
        CP_COMMIT();
    };

    const int b_row = (lane & 7) + ((lane >> 4) & 1) * 8;
    const int b_k   = ((lane >> 3) & 1) * 16;

    float oacc[8][4];
#pragma unroll
    for (int nt = 0; nt < 8; nt++)
#pragma unroll
        for (int e = 0; e < 4; e++) oacc[nt][e] = 0.f;
    float m_r[2] = {-1e30f, -1e30f};
    float l_r[2] = {0.f, 0.f};

    const int nch = causal ? ((q0 >> 6) + 2) : 8;
    load(0, 0);

    for (int c = 0; c < nch; c++) {
        const int s = c & 1;
        if (c + 1 < nch) { load(c + 1, s ^ 1); CP_WAIT(1); }
        else CP_WAIT(0);
        __syncthreads();
        const uint32_t rb = sb + s * 40960;

        float sacc[8][4];
#pragma unroll
        for (int nt = 0; nt < 8; nt++)
#pragma unroll
            for (int e = 0; e < 4; e++) sacc[nt][e] = 0.f;
#pragma unroll
        for (int kk = 0; kk < 4; kk++) {
            uint32_t ql4[4];
            ldm4(ql4, QLO + (kk >> 1) * 10240 + (wrow + a_row) * 80 + (kk & 1) * 32 + a_k);
#pragma unroll
            for (int np = 0; np < 4; np++) {
                uint32_t rh[4], rl[4];
                uint32_t bd = rb + (kk >> 1) * 5120 + (b_row + np * 16) * 80
                            + (kk & 1) * 32 + b_k;
                ldm4(rh, bd);
                ldm4(rl, bd + 10240);
                uint32_t bh0[2] = {rh[0], rh[1]}, bh1[2] = {rh[2], rh[3]};
                uint32_t bl0[2] = {rl[0], rl[1]}, bl1[2] = {rl[2], rl[3]};
                mma_bf16(sacc[2 * np],     qfh[kk], bh0);
                mma_bf16(sacc[2 * np],     qfh[kk], bl0);
                mma_bf16(sacc[2 * np],     ql4,     bh0);
                mma_bf16(sacc[2 * np + 1], qfh[kk], bh1);
                mma_bf16(sacc[2 * np + 1], qfh[kk], bl1);
                mma_bf16(sacc[2 * np + 1], ql4,     bh1);
            }
        }

        const int sk0 = c * 64;
        const int row0 = q0 + wrow + (lane >> 2);
        const int colb = (lane & 3) * 2;
#pragma unroll
        for (int nt = 0; nt < 8; nt++)
#pragma unroll
            for (int e = 0; e < 4; e++) {
                int col = sk0 + nt * 8 + colb + (e & 1);
                int row = row0 + (e >> 1) * 8;
                float v = sacc[nt][e] * 0.125f + msk[col];
                if (causal && col > row) v = -1e30f;
                sacc[nt][e] = v;
            }

        float mx[2] = {-1e30f, -1e30f};
#pragma unroll
        for (int nt = 0; nt < 8; nt++)
#pragma unroll
            for (int e = 0; e < 4; e++)
                mx[e >> 1] = fmaxf(mx[e >> 1], sacc[nt][e]);
#pragma unroll
        for (int r = 0; r < 2; r++) {
            mx[r] = fmaxf(mx[r], __shfl_xor_sync(0xffffffffu, mx[r], 1));
            mx[r] = fmaxf(mx[r], __shfl_xor_sync(0xffffffffu, mx[r], 2));
        }
        float corr[2], mnew[2];
#pragma unroll
        for (int r = 0; r < 2; r++) {
            mnew[r] = fmaxf(m_r[r], mx[r]);
            corr[r] = __expf(m_r[r] - mnew[r]);
            m_r[r] = mnew[r];
        }
        float sum[2] = {0.f, 0.f};
#pragma unroll
        for (int nt = 0; nt < 8; nt++)
#pragma unroll
            for (int e = 0; e < 4; e++) {
                float p = __expf(sacc[nt][e] - mnew[e >> 1]);
                sacc[nt][e] = p;
                sum[e >> 1] += p;
            }
#pragma unroll
        for (int r = 0; r < 2; r++) {
            sum[r] += __shfl_xor_sync(0xffffffffu, sum[r], 1);
            sum[r] += __shfl_xor_sync(0xffffffffu, sum[r], 2);
            l_r[r] = l_r[r] * corr[r] + sum[r];
        }
#pragma unroll
        for (int nt = 0; nt < 8; nt++)
#pragma unroll
            for (int e = 0; e < 4; e++) oacc[nt][e] *= corr[e >> 1];

#pragma unroll
        for (int g = 0; g < 4; g++) {
            uint32_t pah[4], pal[4];
            packsplit(sacc[2 * g][0],     sacc[2 * g][1],     pah[0], pal[0]);
            packsplit(sacc[2 * g][2],     sacc[2 * g][3],     pah[1], pal[1]);
            packsplit(sacc[2 * g + 1][0], sacc[2 * g + 1][1], pah[2], pal[2]);
            packsplit(sacc[2 * g + 1][2], sacc[2 * g + 1][3], pah[3], pal[3]);
#pragma unroll
            for (int np = 0; np < 4; np++) {
                uint32_t rh[4], rl[4];
                uint32_t vd = rb + 20480 + (g >> 1) * 5120 + (b_row + np * 16) * 80
                            + (g & 1) * 32 + b_k;
                ldm4(rh, vd);
                ldm4(rl, vd + 10240);
                uint32_t bh0[2] = {rh[0], rh[1]}, bh1[2] = {rh[2], rh[3]};
                uint32_t bl0[2] = {rl[0], rl[1]}, bl1[2] = {rl[2], rl[3]};
                mma_bf16(oacc[2 * np],     pah, bh0);
                mma_bf16(oacc[2 * np],     pah, bl0);
                mma_bf16(oacc[2 * np],     pal, bh0);
                mma_bf16(oacc[2 * np + 1], pah, bh1);
                mma_bf16(oacc[2 * np + 1], pah, bl1);
                mma_bf16(oacc[2 * np + 1], pal, bh1);
            }
        }
        __syncthreads();
    }

#pragma unroll
    for (int r = 0; r < 2; r++) {
        float inv = 1.f / l_r[r];
        int row = q0 + wrow + (lane >> 2) + r * 8;
        long long base = ((long long)(b * 512 + row)) * 512 + h * 64 + (lane & 3) * 2;
#pragma unroll
        for (int nt = 0; nt < 8; nt++) {
            float v0 = oacc[nt][r * 2 + 0] * inv;
            float v1 = oacc[nt][r * 2 + 1] * inv;
            bf16 h0 = __float2bfloat16(v0);
            bf16 h1 = __float2bfloat16(v1);
            uint32_t hi = packbf(h0, h1);
            uint32_t lo = packbf(__float2bfloat16(v0 - __bfloat162float(h0)),
                                 __float2bfloat16(v1 - __bfloat162float(h1)));
            *reinterpret_cast<uint32_t*>(Oh + base + nt * 8) = hi;
            *reinterpret_cast<uint32_t*>(Ol + base + nt * 8) = lo;
        }
    }
}

// ---------------- merged weight transpose+split (3 sources, contiguous out) --
__global__ void k_tsplitw(const float* __restrict__ inA, const float* __restrict__ inB,
                          const float* __restrict__ inC, bf16* __restrict__ oh,
                          bf16* __restrict__ ol, int K, int N, int per)
{
    __shared__ float t[32][33];
    const int z = blockIdx.z;
    const float* in = (z < per) ? inA : ((z < 2 * per) ? inB : inC);
    const int zz = z % per;
    const long long ib = (long long)zz * K * N;
    const long long ob = (long long)z * K * N;
    const int n0 = blockIdx.x * 32, k0 = blockIdx.y * 32;
    const int tx = threadIdx.x, ty = threadIdx.y;

    for (int r = ty; r < 32; r += 8) {
        int k = k0 + r, n = n0 + tx;
        t[r][tx] = (k < K && n < N) ? in[ib + (long long)k * N + n] : 0.f;
    }
    __syncthreads();
    for (int r = ty; r < 32; r += 8) {
        int n = n0 + r, k = k0 + tx;
        if (n < N && k < K) {
            float x = t[tx][r];
            bf16 hi = __float2bfloat16(x);
            oh[ob + (long long)n * K + k] = hi;
            ol[ob + (long long)n * K + k] = __float2bfloat16(x - __bfloat162float(hi));
        }
    }
}

// ---------------- V^T split from qkv bf16 buffer ------------------------------
__global__ void k_vtsplit(const bf16* __restrict__ ih, const bf16* __restrict__ il,
                          bf16* __restrict__ oh, bf16* __restrict__ ol)
{
    __shared__ float t[32][33];
    const int z = blockIdx.z, b = z >> 3, h = z & 7;
    const int n0 = blockIdx.x * 32, s0 = blockIdx.y * 32;
    const int tx = threadIdx.x, ty = threadIdx.y;
    const long long ib = (long long)b * 512 * 1536 + 1024 + h * 64;
    const long long ob = (long long)z * 64 * 512;

    for (int r = ty; r < 32; r += 8) {
        long long off = ib + (long long)(s0 + r) * 1536 + n0 + tx;
        t[r][tx] = __bfloat162float(ih[off]) + __bfloat162float(il[off]);
    }
    __syncthreads();
    for (int r = ty; r < 32; r += 8) {
        float x = t[tx][r];
        bf16 hi = __float2bfloat16(x);
        long long o = ob + (long long)(n0 + r) * 512 + s0 + tx;
        oh[o] = hi;
        ol[o] = __float2bfloat16(x - __bfloat162float(hi));
    }
}

// ---------------- embedding + posenc (+ split) -------------------------------
__global__ void k_embed(const int* __restrict__ tok, const float* __restrict__ emb,
                        float* __restrict__ out, bf16* __restrict__ oh,
                        bf16* __restrict__ ol)
{
    int idx = blockIdx.x * blockDim.x + threadIdx.x;
    if (idx >= BSc * Dc) return;
    int d  = idx & (Dc - 1);
    int bs = idx >> 9;
    int s  = bs & (Sc - 1);
    int t  = tok[bs];
    int i2 = d & ~1;
    float div = expf((float)i2 * (-9.210340371976184f / (float)Dc));
    float ang = (float)s * div;
    float pe  = (d & 1) ? cosf(ang) : sinf(ang);
    float v = emb[(size_t)t * Dc + d] + pe;
    out[idx] = v;
    bf16 hi = __float2bfloat16(v);
    oh[idx] = hi;
    ol[idx] = __float2bfloat16(v - __bfloat162float(hi));
}

// ---------------- residual + LayerNorm (+ split out) -------------------------
__global__ __launch_bounds__(256) void k_lnres(
    const float* __restrict__ X, const float* __restrict__ Dl,
    const float* __restrict__ g, const float* __restrict__ bt,
    float* __restrict__ Out, bf16* __restrict__ oh, bf16* __restrict__ ol)
{
    int warp = threadIdx.x >> 5, lane = threadIdx.x & 31;
    size_t row = (size_t)blockIdx.x * 8 + warp;
    const float* px = X  + row * Dc;
    const float* pd = Dl + row * Dc;
    float v[16];
    float s = 0.f;
#pragma unroll
    for (int i = 0; i < 16; i++) { v[i] = px[lane + i * 32] + pd[lane + i * 32]; s += v[i]; }
#pragma unroll
    for (int o = 16; o; o >>= 1) s += __shfl_xor_sync(0xffffffffu, s, o);
    float mu = s * (1.f / (float)Dc);
    float var = 0.f;
#pragma unroll
    for (int i = 0; i < 16; i++) { float d = v[i] - mu; var += d * d; }
#pragma unroll
    for (int o = 16; o; o >>= 1) var += __shfl_xor_sync(0xffffffffu, var, o);
    var *= (1.f / (float)Dc);
    float inv = rsqrtf(var + 1e-5f);
#pragma unroll
    for (int i = 0; i < 16; i++) {
        int c = lane + i * 32;
        float o = (v[i] - mu) * inv * g[c] + bt[c];
        Out[row * Dc + c] = o;
        bf16 hi = __float2bfloat16(o);
        oh[row * Dc + c] = hi;
        ol[row * Dc + c] = __float2bfloat16(o - __bfloat162float(hi));
    }
}

// =============================================================================
extern "C" void kernel_launch(void* const* d_in, const int* in_sizes, int n_in,
                              void* d_out, int out_size)
{
    const int*   src      = (const int*)  d_in[0];
    const int*   tgt      = (const int*)  d_in[1];
    const float* src_emb  = (const float*)d_in[2];
    const float* tgt_emb  = (const float*)d_in[3];
    const float* e_qkvo_w = (const float*)d_in[4];
    const float* e_qkvo_b = (const float*)d_in[5];
    const float* e_ff1_w  = (const float*)d_in[6];
    const float* e_ff1_b  = (const float*)d_in[7];
    const float* e_ff2_w  = (const float*)d_in[8];
    const float* e_ff2_b  = (const float*)d_in[9];
    const float* e_ln_g   = (const float*)d_in[10];
    const float* e_ln_b   = (const float*)d_in[11];
    const float* d_sa_w   = (const float*)d_in[12];
    const float* d_sa_b   = (const float*)d_in[13];
    const float* d_ca_w   = (const float*)d_in[14];
    const float* d_ca_b   = (const float*)d_in[15];
    const float* d_ff1_w  = (const float*)d_in[16];
    const float* d_ff1_b  = (const float*)d_in[17];
    const float* d_ff2_w  = (const float*)d_in[18];
    const float* d_ff2_b  = (const float*)d_in[19];
    const float* d_ln_g   = (const float*)d_in[20];
    const float* d_ln_b   = (const float*)d_in[21];
    const float* out_w    = (const float*)d_in[22];
    const float* out_b    = (const float*)d_in[23];
    float* out = (float*)d_out;

    float *px, *py, *pa;
    bf16 *wh, *wl, *qvh, *qvl, *ah, *al, *dyh, *dyl, *fh, *fl, *vth, *vtl,
         *th, *tl, *xeh, *xel;
    cudaGetSymbolAddress((void**)&px,  g_x);
    cudaGetSymbolAddress((void**)&py,  g_y);
    cudaGetSymbolAddress((void**)&pa,  g_a);
    cudaGetSymbolAddress((void**)&wh,  g_wh);
    cudaGetSymbolAddress((void**)&wl,  g_wl);
    cudaGetSymbolAddress((void**)&qvh, g_qkvh);
    cudaGetSymbolAddress((void**)&qvl, g_qkvl);
    cudaGetSymbolAddress((void**)&ah,  g_ah);
    cudaGetSymbolAddress((void**)&al,  g_al);
    cudaGetSymbolAddress((void**)&dyh, g_dyh);
    cudaGetSymbolAddress((void**)&dyl, g_dyl);
    cudaGetSymbolAddress((void**)&fh,  g_fh);
    cudaGetSymbolAddress((void**)&fl,  g_fl);
    cudaGetSymbolAddress((void**)&vth, g_vth);
    cudaGetSymbolAddress((void**)&vtl, g_vtl);
    cudaGetSymbolAddress((void**)&th,  g_th);
    cudaGetSymbolAddress((void**)&tl,  g_tl);
    cudaGetSymbolAddress((void**)&xeh, g_xeh);
    cudaGetSymbolAddress((void**)&xel, g_xel);

    const int SMEM64 = 3 * (2 * 128 * 80 + 2 * 64 * 80);   // 92160 -> 2 CTAs/SM
    const int FLASH_SMEM = 104448;
    cudaFuncSetAttribute((const void*)k_tgemm<64>,
                         cudaFuncAttributeMaxDynamicSharedMemorySize, SMEM64);
    cudaFuncSetAttribute((const void*)k_flash,
                         cudaFuncAttributeMaxDynamicSharedMemorySize, FLASH_SMEM);

    // ---- launchers ----------------------------------------------------------
    auto dense = [&](const bf16* Axh, const bf16* Axl, int lda, long long woff,
                     int ldb, float* C, bf16* Oh, bf16* Ol, int ldc,
                     const float* bias, int relu, int N, int K) {
        dim3 g((N + 63) / 64, BSc / 128, 1);
        k_tgemm<64><<<g, 256, SMEM64>>>(Axh, Axl, lda, 0, 0,
                                        wh + woff, wl + woff, ldb, 0, 0,
                                        C, Oh, Ol, ldc, 0, 0,
                                        bias, relu, N, K, 1.f);
    };
    auto flash = [&](int causal, const int* kt) {
        k_flash<<<dim3(4, 64), 256, FLASH_SMEM>>>(qvh, qvl, qvh + 512, qvl + 512,
                                                  vth, vtl, th, tl, kt, causal);
    };
    auto vtsplit = [&]() {
        k_vtsplit<<<dim3(2, 16, 64), dim3(32, 8)>>>(qvh, qvl, vth, vtl);
    };
    const int ln_blocks = BSc / 8;
    const long long DD = (long long)Dc * Dc;

    // ---- prologue (launch #4 = dense GEMM, captured by ncu) ------------------
    k_tsplitw<<<dim3(16, 16, 72), dim3(32, 8)>>>(e_qkvo_w, d_sa_w, d_ca_w,
                                                 wh, wl, 512, 512, 24);
    k_embed<<<(BSc * Dc + 255) / 256, 256>>>(src, src_emb, px, ah, al);
    k_tsplitw<<<dim3(64, 16, 12), dim3(32, 8)>>>(e_ff1_w, d_ff1_w, d_ff1_w,
                                                 wh + OFF_FF1E, wl + OFF_FF1E,
                                                 512, 2048, 6);
    dense(ah, al, Dc, OFF_QKVO_E, Dc, nullptr, qvh, qvl, 1536, e_qkvo_b, 0, 1536, Dc);
    k_tsplitw<<<dim3(16, 64, 12), dim3(32, 8)>>>(e_ff2_w, d_ff2_w, d_ff2_w,
                                                 wh + OFF_FF2E, wl + OFF_FF2E,
                                                 2048, 512, 6);
    k_tsplitw<<<dim3(313, 16, 1), dim3(32, 8)>>>(out_w, out_w, out_w,
                                                 wh + OFF_OUT, wl + OFF_OUT,
                                                 512, 10000, 1);
    k_embed<<<(BSc * Dc + 255) / 256, 256>>>(tgt, tgt_emb, py, dyh, dyl);

    // ================= encoder =================
    for (int l = 0; l < Lc; l++) {
        long long w = OFF_QKVO_E + (long long)l * 4 * DD;
        const float* b = e_qkvo_b + (size_t)l * 4 * Dc;
        if (l > 0)
            dense(ah, al, Dc, w, Dc, nullptr, qvh, qvl, 1536, b, 0, 1536, Dc);
        vtsplit();
        flash(0, src);
        dense(th, tl, Dc, w + 3 * DD, Dc, pa, nullptr, nullptr, Dc, b + 3 * Dc, 0, Dc, Dc);
        k_lnres<<<ln_blocks, 256>>>(px, pa, e_ln_g + (size_t)l * 2 * Dc,
                                    e_ln_b + (size_t)l * 2 * Dc, px, ah, al);
        dense(ah, al, Dc, OFF_FF1E + (long long)l * Dc * FFc, Dc,
              nullptr, fh, fl, FFc, e_ff1_b + (size_t)l * FFc, 1, FFc, Dc);
        dense(fh, fl, FFc, OFF_FF2E + (long long)l * Dc * FFc, FFc,
              pa, nullptr, nullptr, Dc, e_ff2_b + (size_t)l * Dc, 0, Dc, FFc);
        bf16* oh2 = (l == Lc - 1) ? xeh : ah;
        bf16* ol2 = (l == Lc - 1) ? xel : al;
        k_lnres<<<ln_blocks, 256>>>(px, pa, e_ln_g + (size_t)l * 2 * Dc + Dc,
                                    e_ln_b + (size_t)l * 2 * Dc + Dc, px, oh2, ol2);
    }

    // ================= decoder =================
    for (int l = 0; l < Lc; l++) {
        long long ws = OFF_SA + (long long)l * 4 * DD;
        const float* bs = d_sa_b + (size_t)l * 4 * Dc;
        const bf16* ain_h = (l == 0) ? dyh : ah;
        const bf16* ain_l = (l == 0) ? dyl : al;
        dense(ain_h, ain_l, Dc, ws, Dc, nullptr, qvh, qvl, 1536, bs, 0, 1536, Dc);
        vtsplit();
        flash(1, nullptr);
        dense(th, tl, Dc, ws + 3 * DD, Dc, pa, nullptr, nullptr, Dc, bs + 3 * Dc, 0, Dc, Dc);
        k_lnres<<<ln_blocks, 256>>>(py, pa, d_ln_g + (size_t)l * 3 * Dc,
                                    d_ln_b + (size_t)l * 3 * Dc, py, ah, al);

        long long wc = OFF_CA + (long long)l * 4 * DD;
        const float* bc = d_ca_b + (size_t)l * 4 * Dc;
        dense(ah,  al,  Dc, wc,      Dc, nullptr, qvh, qvl, 1536, bc, 0, Dc, Dc);
        dense(xeh, xel, Dc, wc + DD, Dc, nullptr, qvh + 512, qvl + 512, 1536,
              bc + Dc, 0, 1024, Dc);
        vtsplit();
        flash(0, tgt);
        dense(th, tl, Dc, wc + 3 * DD, Dc, pa, nullptr, nullptr, Dc, bc + 3 * Dc, 0, Dc, Dc);
        k_lnres<<<ln_blocks, 256>>>(py, pa, d_ln_g + (size_t)l * 3 * Dc + Dc,
                                    d_ln_b + (size_t)l * 3 * Dc + Dc, py, ah, al);

        dense(ah, al, Dc, OFF_FF1D + (long long)l * Dc * FFc, Dc,
              nullptr, fh, fl, FFc, d_ff1_b + (size_t)l * FFc, 1, FFc, Dc);
        dense(fh, fl, FFc, OFF_FF2D + (long long)l * Dc * FFc, FFc,
              pa, nullptr, nullptr, Dc, d_ff2_b + (size_t)l * Dc, 0, Dc, FFc);
        k_lnres<<<ln_blocks, 256>>>(py, pa, d_ln_g + (size_t)l * 3 * Dc + 2 * Dc,
                                    d_ln_b + (size_t)l * 3 * Dc + 2 * Dc, py, ah, al);
    }

    // ================= output projection =================
    dense(ah, al, Dc, OFF_OUT, Dc, out, nullptr, nullptr, Vc, out_b, 0, Vc, Dc);
}

// round 17
// speedup vs baseline: 1.5567x; 1.0196x over previous
#include <cuda_runtime.h>
#include <cuda_bf16.h>
#include <cuda_fp16.h>
#include <math.h>
#include <stdint.h>

typedef __nv_bfloat16 bf16;
typedef __half f16;

static constexpr int Bc  = 8;
static constexpr int Sc  = 512;
static constexpr int Dc  = 512;
static constexpr int DKc = 64;
static constexpr int FFc = 2048;
static constexpr int Vc  = 10000;
static constexpr int Lc  = 6;
static constexpr int BSc = Bc * Sc;   // 4096

// ---------------- weight offsets (transposed bf16 [N,K] layout) --------------
static constexpr long long OFF_QKVO_E = 0;
static constexpr long long OFF_SA     = 24LL * 262144;
static constexpr long long OFF_CA     = 48LL * 262144;
static constexpr long long OFF_FF1E   = 72LL * 262144;
static constexpr long long OFF_FF1D   = OFF_FF1E + 6LL * 1048576;
static constexpr long long OFF_FF2E   = OFF_FF1D + 6LL * 1048576;
static constexpr long long OFF_FF2D   = OFF_FF2E + 6LL * 1048576;
static constexpr long long W_TOTAL    = OFF_FF2D + 6LL * 1048576;

// ---------------- scratch ----------------------------------------------------
__device__ float g_x [BSc * Dc];
__device__ float g_y [BSc * Dc];
__device__ float g_a [BSc * Dc];

__device__ bf16 g_wh[W_TOTAL];
__device__ bf16 g_wl[W_TOTAL];
__device__ bf16 g_qkvh[(size_t)BSc * 1536], g_qkvl[(size_t)BSc * 1536];
__device__ bf16 g_ah [BSc * Dc],  g_al [BSc * Dc];
__device__ bf16 g_dyh[BSc * Dc],  g_dyl[BSc * Dc];    // decoder embed split
__device__ bf16 g_fh [BSc * FFc], g_fl [BSc * FFc];
__device__ bf16 g_vth[BSc * Dc],  g_vtl[BSc * Dc];    // V^T per head [bh][64][512]
__device__ bf16 g_th [BSc * Dc],  g_tl [BSc * Dc];
__device__ bf16 g_xeh[BSc * Dc],  g_xel[BSc * Dc];

// fp16 path for the final output projection
__device__ f16 g_owh[(long long)Vc * Dc], g_owl[(long long)Vc * Dc];
__device__ f16 g_a16[BSc * Dc];

// ---------------- PTX helpers ------------------------------------------------
__device__ __forceinline__ uint32_t smem_u32(const void* p) {
    uint32_t a;
    asm("{ .reg .u64 t; cvta.to.shared.u64 t, %1; cvt.u32.u64 %0, t; }"
        : "=r"(a) : "l"(p));
    return a;
}
__device__ __forceinline__ void cpasync16(uint32_t dst, const void* src, int sz) {
    asm volatile("cp.async.cg.shared.global [%0], [%1], 16, %2;\n"
                 :: "r"(dst), "l"(src), "r"(sz));
}
#define CP_COMMIT() asm volatile("cp.async.commit_group;\n" ::: "memory")
#define CP_WAIT(n)  asm volatile("cp.async.wait_group %0;\n" :: "n"(n) : "memory")

__device__ __forceinline__ void ldm4(uint32_t* r, uint32_t addr) {
    asm volatile("ldmatrix.sync.aligned.m8n8.x4.shared.b16 {%0,%1,%2,%3}, [%4];"
                 : "=r"(r[0]), "=r"(r[1]), "=r"(r[2]), "=r"(r[3]) : "r"(addr));
}
__device__ __forceinline__ void mma_bf16(float* c, const uint32_t* a, const uint32_t* b) {
    asm volatile(
        "mma.sync.aligned.m16n8k16.row.col.f32.bf16.bf16.f32 "
        "{%0,%1,%2,%3}, {%4,%5,%6,%7}, {%8,%9}, {%0,%1,%2,%3};"
        : "+f"(c[0]), "+f"(c[1]), "+f"(c[2]), "+f"(c[3])
        : "r"(a[0]), "r"(a[1]), "r"(a[2]), "r"(a[3]), "r"(b[0]), "r"(b[1]));
}
__device__ __forceinline__ void mma_f16(float* c, const uint32_t* a, const uint32_t* b) {
    asm volatile(
        "mma.sync.aligned.m16n8k16.row.col.f32.f16.f16.f32 "
        "{%0,%1,%2,%3}, {%4,%5,%6,%7}, {%8,%9}, {%0,%1,%2,%3};"
        : "+f"(c[0]), "+f"(c[1]), "+f"(c[2]), "+f"(c[3])
        : "r"(a[0]), "r"(a[1]), "r"(a[2]), "r"(a[3]), "r"(b[0]), "r"(b[1]));
}
__device__ __forceinline__ uint32_t packbf(bf16 x, bf16 y) {
    uint16_t ux = *reinterpret_cast<uint16_t*>(&x);
    uint16_t uy = *reinterpret_cast<uint16_t*>(&y);
    return (uint32_t)ux | ((uint32_t)uy << 16);
}
__device__ __forceinline__ void packsplit(float x, float y, uint32_t& hi, uint32_t& lo) {
    bf16 xh = __float2bfloat16(x);
    bf16 yh = __float2bfloat16(y);
    bf16 xl = __float2bfloat16(x - __bfloat162float(xh));
    bf16 yl = __float2bfloat16(y - __bfloat162float(yh));
    hi = packbf(xh, yh);
    lo = packbf(xl, yl);
}

// ---------------- split-bf16 HMMA GEMM (BK=32, 3-stage) ----------------------
// NT=64: 256 thr, 8 warps (4m x 2n), warp tile 32x32, 2 CTAs/SM.  (R13 best)
template <int NT>
__global__ __launch_bounds__(NT == 128 ? 512 : 256, NT == 128 ? 1 : 2) void k_tgemm(
    const bf16* __restrict__ Ah, const bf16* __restrict__ Al, int lda,
    long long sAb, long long sAh,
    const bf16* __restrict__ Bh, const bf16* __restrict__ Bl, int ldb,
    long long sBb, long long sBh,
    float* __restrict__ C, bf16* __restrict__ Oh, bf16* __restrict__ Ol,
    int ldc, long long sCb, long long sCh,
    const float* __restrict__ bias, int relu, int N, int K, float scale)
{
    constexpr int NTH   = (NT == 128) ? 512 : 256;
    constexpr int ATILE = 128 * 80;
    constexpr int BTILE = NT * 80;
    constexpr int S_AH = 0, S_AL = ATILE, S_BH = 2 * ATILE, S_BL = 2 * ATILE + BTILE;
    constexpr int STAGE = 2 * ATILE + 2 * BTILE;

    extern __shared__ char smem[];
    const uint32_t sb = smem_u32(smem);
    const int tid = threadIdx.x, lane = tid & 31, wid = tid >> 5;
    const int wm = wid & 3, wn = wid >> 2;
    const int z = blockIdx.z, b = z >> 3, h = z & 7;
    const int m0 = blockIdx.y * 128, n0 = blockIdx.x * NT;

    const bf16* pAh = Ah + (long long)b * sAb + (long long)h * sAh;
    const bf16* pAl = Al + (long long)b * sAb + (long long)h * sAh;
    const bf16* pBh = Bh + (long long)b * sBb + (long long)h * sBh;
    const bf16* pBl = Bl + (long long)b * sBb + (long long)h * sBh;

    auto load = [&](int c, int s) {
        const int k0 = c * 32;
        const uint32_t base = sb + s * STAGE;
        for (int i = tid; i < 128 * 4; i += NTH) {
            int r = i >> 2, sub = i & 3;
            long long off = (long long)(m0 + r) * lda + k0 + sub * 8;
            uint32_t d = base + r * 80 + sub * 16;
            cpasync16(d + S_AH, pAh + off, 16);
            cpasync16(d + S_AL, pAl + off, 16);
        }
        for (int i = tid; i < NT * 4; i += NTH) {
            int r = i >> 2, sub = i & 3;
            int n = n0 + r;
            int sz = (n < N) ? 16 : 0;
            int nc = (n < N) ? n : 0;
            long long off = (long long)nc * ldb + k0 + sub * 8;
            uint32_t d = base + r * 80 + sub * 16;
            cpasync16(d + S_BH, pBh + off, sz);
            cpasync16(d + S_BL, pBl + off, sz);
        }
        CP_COMMIT();
    };

    float acc[2][4][4];
#pragma unroll
    for (int mt = 0; mt < 2; mt++)
#pragma unroll
        for (int nt = 0; nt < 4; nt++)
#pragma unroll
            for (int j = 0; j < 4; j++) acc[mt][nt][j] = 0.f;

    const int a_row = wm * 32 + (lane & 15);
    const int a_k   = ((lane >> 4) & 1) * 16;
    const int b_row = wn * 32 + (lane & 7) + ((lane >> 4) & 1) * 8;
    const int b_k   = ((lane >> 3) & 1) * 16;

    const int nch = K >> 5;
    load(0, 0);
    if (nch > 1) load(1, 1);

    for (int c = 0; c < nch; c++) {
        const int s = c % 3;
        if (c + 2 < nch) { load(c + 2, (c + 2) % 3); CP_WAIT(2); }
        else if (c + 1 < nch) CP_WAIT(1);
        else CP_WAIT(0);
        __syncthreads();
        const uint32_t st = sb + s * STAGE;
#pragma unroll
        for (int ks = 0; ks < 2; ks++) {
            uint32_t afh[2][4], afl[2][4], bfh[4][2], bfl[4][2];
#pragma unroll
            for (int mt = 0; mt < 2; mt++) {
                uint32_t ad = st + (a_row + mt * 16) * 80 + ks * 32 + a_k;
                ldm4(afh[mt], ad + S_AH);
                ldm4(afl[mt], ad + S_AL);
            }
#pragma unroll
            for (int np = 0; np < 2; np++) {
                uint32_t bd = st + (b_row + np * 16) * 80 + ks * 32 + b_k;
                uint32_t r[4];
                ldm4(r, bd + S_BH);
                bfh[np * 2][0] = r[0]; bfh[np * 2][1] = r[1];
                bfh[np * 2 + 1][0] = r[2]; bfh[np * 2 + 1][1] = r[3];
                ldm4(r, bd + S_BL);
                bfl[np * 2][0] = r[0]; bfl[np * 2][1] = r[1];
                bfl[np * 2 + 1][0] = r[2]; bfl[np * 2 + 1][1] = r[3];
            }
#pragma unroll
            for (int mt = 0; mt < 2; mt++)
#pragma unroll
                for (int nt = 0; nt < 4; nt++) {
                    mma_bf16(acc[mt][nt], afh[mt], bfh[nt]);
                    mma_bf16(acc[mt][nt], afh[mt], bfl[nt]);
                    mma_bf16(acc[mt][nt], afl[mt], bfh[nt]);
                }
        }
        __syncthreads();
    }

    const int l4 = lane >> 2, l2 = (lane & 3) * 2;
    const long long coff = (long long)b * sCb + (long long)h * sCh;
#pragma unroll
    for (int mt = 0; mt < 2; mt++) {
#pragma unroll
        for (int h2 = 0; h2 < 2; h2++) {
            const int row = m0 + wm * 32 + mt * 16 + h2 * 8 + l4;
#pragma unroll
            for (int nt = 0; nt < 4; nt++) {
#pragma unroll
                for (int j = 0; j < 2; j++) {
                    int col = n0 + wn * 32 + nt * 8 + l2 + j;
                    if (col < N) {
                        float v = acc[mt][nt][h2 * 2 + j] * scale;
                        if (bias) v += bias[col];
                        if (relu) v = fmaxf(v, 0.f);
                        long long o = coff + (long long)row * ldc + col;
                        if (C) C[o] = v;
                        if (Oh) {
                            bf16 hi = __float2bfloat16(v);
                            Oh[o] = hi;
                            Ol[o] = __float2bfloat16(v - __bfloat162float(hi));
                        }
                    }
                }
            }
        }
    }
}

// ---------------- fp16 2-term GEMM for the final output projection -----------
// C[4096,N] = A16[4096,K] @ (Bh+Bl)[N,K]^T + bias. A rounded to fp16 (error
// 2^-11, non-compounding); B split to fp16 hi/lo (~exact). 16 MMAs/ks vs 24.
__global__ __launch_bounds__(256, 2) void k_hgemm(
    const f16* __restrict__ A, int lda,
    const f16* __restrict__ Bh, const f16* __restrict__ Bl, int ldb,
    float* __restrict__ C, const float* __restrict__ bias, int N, int K)
{
    constexpr int ATILE = 128 * 80;
    constexpr int BTILE = 64 * 80;
    constexpr int S_A = 0, S_BH = ATILE, S_BL = ATILE + BTILE;
    constexpr int STAGE = ATILE + 2 * BTILE;   // 20480

    extern __shared__ char smem[];
    const uint32_t sb = smem_u32(smem);
    const int tid = threadIdx.x, lane = tid & 31, wid = tid >> 5;
    const int wm = wid & 3, wn = wid >> 2;
    const int m0 = blockIdx.y * 128, n0 = blockIdx.x * 64;

    auto load = [&](int c, int s) {
        const int k0 = c * 32;
        const uint32_t base = sb + s * STAGE;
        for (int i = tid; i < 128 * 4; i += 256) {
            int r = i >> 2, sub = i & 3;
            long long off = (long long)(m0 + r) * lda + k0 + sub * 8;
            cpasync16(base + S_A + r * 80 + sub * 16, A + off, 16);
        }
        for (int i = tid; i < 64 * 4; i += 256) {
            int r = i >> 2, sub = i & 3;
            int n = n0 + r;
            int sz = (n < N) ? 16 : 0;
            int nc = (n < N) ? n : 0;
            long long off = (long long)nc * ldb + k0 + sub * 8;
            uint32_t d = base + r * 80 + sub * 16;
            cpasync16(d + S_BH, Bh + off, sz);
            cpasync16(d + S_BL, Bl + off, sz);
        }
        CP_COMMIT();
    };

    float acc[2][4][4];
#pragma unroll
    for (int mt = 0; mt < 2; mt++)
#pragma unroll
        for (int nt = 0; nt < 4; nt++)
#pragma unroll
            for (int j = 0; j < 4; j++) acc[mt][nt][j] = 0.f;

    const int a_row = wm * 32 + (lane & 15);
    const int a_k   = ((lane >> 4) & 1) * 16;
    const int b_row = wn * 32 + (lane & 7) + ((lane >> 4) & 1) * 8;
    const int b_k   = ((lane >> 3) & 1) * 16;

    const int nch = K >> 5;
    load(0, 0);
    if (nch > 1) load(1, 1);

    for (int c = 0; c < nch; c++) {
        const int s = c % 3;
        if (c + 2 < nch) { load(c + 2, (c + 2) % 3); CP_WAIT(2); }
        else if (c + 1 < nch) CP_WAIT(1);
        else CP_WAIT(0);
        __syncthreads();
        const uint32_t st = sb + s * STAGE;
#pragma unroll
        for (int ks = 0; ks < 2; ks++) {
            uint32_t af[2][4], bfh[4][2], bfl[4][2];
#pragma unroll
            for (int mt = 0; mt < 2; mt++)
                ldm4(af[mt], st + S_A + (a_row + mt * 16) * 80 + ks * 32 + a_k);
#pragma unroll
            for (int np = 0; np < 2; np++) {
                uint32_t bd = st + (b_row + np * 16) * 80 + ks * 32 + b_k;
                uint32_t r[4];
                ldm4(r, bd + S_BH);
                bfh[np * 2][0] = r[0]; bfh[np * 2][1] = r[1];
                bfh[np * 2 + 1][0] = r[2]; bfh[np * 2 + 1][1] = r[3];
                ldm4(r, bd + S_BL);
                bfl[np * 2][0] = r[0]; bfl[np * 2][1] = r[1];
                bfl[np * 2 + 1][0] = r[2]; bfl[np * 2 + 1][1] = r[3];
            }
#pragma unroll
            for (int mt = 0; mt < 2; mt++)
#pragma unroll
                for (int nt = 0; nt < 4; nt++) {
                    mma_f16(acc[mt][nt], af[mt], bfh[nt]);
                    mma_f16(acc[mt][nt], af[mt], bfl[nt]);
                }
        }
        __syncthreads();
    }

    const int l4 = lane >> 2, l2 = (lane & 3) * 2;
#pragma unroll
    for (int mt = 0; mt < 2; mt++) {
#pragma unroll
        for (int h2 = 0; h2 < 2; h2++) {
            const int row = m0 + wm * 32 + mt * 16 + h2 * 8 + l4;
#pragma unroll
            for (int nt = 0; nt < 4; nt++) {
#pragma unroll
                for (int j = 0; j < 2; j++) {
                    int col = n0 + wn * 32 + nt * 8 + l2 + j;
                    if (col < N)
                        C[(long long)row * N + col] = acc[mt][nt][h2 * 2 + j] + bias[col];
                }
            }
        }
    }
}

// ---------------- fused flash attention (R6 datapath, unchanged) -------------
__global__ __launch_bounds__(256, 2) void k_flash(
    const bf16* __restrict__ Qh, const bf16* __restrict__ Ql,
    const bf16* __restrict__ Kh, const bf16* __restrict__ Kl,
    const bf16* __restrict__ Vth, const bf16* __restrict__ Vtl,
    bf16* __restrict__ Oh, bf16* __restrict__ Ol,
    const int* __restrict__ keytok, int causal)
{
    extern __shared__ char smem[];
    const uint32_t sb = smem_u32(smem);
    const int tid = threadIdx.x, lane = tid & 31, wid = tid >> 5;
    const int z = blockIdx.y, b = z >> 3, h = z & 7;
    const int q0 = blockIdx.x * 128;
    const int wrow = wid * 16;
    const uint32_t QLO = sb + 81920;
    float* msk = (float*)(smem + 102400);

    for (int i = tid; i < 128 * 8; i += 256) {
        int r = i >> 3, c = i & 7;
        long long off = ((long long)(b * 512 + q0 + r)) * 1536 + h * 64 + c * 8;
        uint32_t d = (uint32_t)((c >> 2) * 10240 + r * 80 + (c & 3) * 16);
        cpasync16(sb + d, Qh + off, 16);
        cpasync16(QLO + d, Ql + off, 16);
    }
    CP_COMMIT();
    for (int i = tid; i < 512; i += 256)
        msk[i] = (keytok && keytok[b * 512 + i] == 0) ? -1e30f : 0.f;
    CP_WAIT(0);
    __syncthreads();

    const int a_row = lane & 15;
    const int a_k   = ((lane >> 4) & 1) * 16;
    uint32_t qfh[4][4];
#pragma unroll
    for (int kk = 0; kk < 4; kk++)
        ldm4(qfh[kk], sb + (kk >> 1) * 10240 + (wrow + a_row) * 80 + (kk & 1) * 32 + a_k);
    __syncthreads();

    auto load = [&](int c, int s) {
        const uint32_t rb = sb + s * 40960;
        const int sk0 = c * 64;
        for (int i = tid; i < 64 * 8; i += 256) {
            int r = i >> 3, cc = i & 7;
            uint32_t d = (uint32_t)((cc >> 2) * 5120 + r * 80 + (cc & 3) * 16);
            long long ko = ((long long)(b * 512 + sk0 + r)) * 1536 + h * 64 + cc * 8;
            cpasync16(rb + d,         Kh + ko, 16);
            cpasync16(rb + 10240 + d, Kl + ko, 16);
            long long vo = ((long long)(z * 64 + r)) * 512 + sk0 + cc * 8;
            cpasync16(rb + 20480 + d, Vth + vo, 16);
            cpasync16(rb + 30720 + d, Vtl + vo, 16);
        }
        CP_COMMIT();
    };

    const int b_row = (lane & 7) + ((lane >> 4) & 1) * 8;
    const int b_k   = ((lane >> 3) & 1) * 16;

    float oacc[8][4];
#pragma unroll
    for (int nt = 0; nt < 8; nt++)
#pragma unroll
        for (int e = 0; e < 4; e++) oacc[nt][e] = 0.f;
    float m_r[2] = {-1e30f, -1e30f};
    float l_r[2] = {0.f, 0.f};

    const int nch = causal ? ((q0 >> 6) + 2) : 8;
    load(0, 0);

    for (int c = 0; c < nch; c++) {
        const int s = c & 1;
        if (c + 1 < nch) { load(c + 1, s ^ 1); CP_WAIT(1); }
        else CP_WAIT(0);
        __syncthreads();
        const uint32_t rb = sb + s * 40960;

        float sacc[8][4];
#pragma unroll
        for (int nt = 0; nt < 8; nt++)
#pragma unroll
            for (int e = 0; e < 4; e++) sacc[nt][e] = 0.f;
#pragma unroll
        for (int kk = 0; kk < 4; kk++) {
            uint32_t ql4[4];
            ldm4(ql4, QLO + (kk >> 1) * 10240 + (wrow + a_row) * 80 + (kk & 1) * 32 + a_k);
#pragma unroll
            for (int np = 0; np < 4; np++) {
                uint32_t rh[4], rl[4];
                uint32_t bd = rb + (kk >> 1) * 5120 + (b_row + np * 16) * 80
                            + (kk & 1) * 32 + b_k;
                ldm4(rh, bd);
                ldm4(rl, bd + 10240);
                uint32_t bh0[2] = {rh[0], rh[1]}, bh1[2] = {rh[2], rh[3]};
                uint32_t bl0[2] = {rl[0], rl[1]}, bl1[2] = {rl[2], rl[3]};
                mma_bf16(sacc[2 * np],     qfh[kk], bh0);
                mma_bf16(sacc[2 * np],     qfh[kk], bl0);
                mma_bf16(sacc[2 * np],     ql4,     bh0);
                mma_bf16(sacc[2 * np + 1], qfh[kk], bh1);
                mma_bf16(sacc[2 * np + 1], qfh[kk], bl1);
                mma_bf16(sacc[2 * np + 1], ql4,     bh1);
            }
        }

        const int sk0 = c * 64;
        const int row0 = q0 + wrow + (lane >> 2);
        const int colb = (lane & 3) * 2;
#pragma unroll
        for (int nt = 0; nt < 8; nt++)
#pragma unroll
            for (int e = 0; e < 4; e++) {
                int col = sk0 + nt * 8 + colb + (e & 1);
                int row = row0 + (e >> 1) * 8;
                float v = sacc[nt][e] * 0.125f + msk[col];
                if (causal && col > row) v = -1e30f;
                sacc[nt][e] = v;
            }

        float mx[2] = {-1e30f, -1e30f};
#pragma unroll
        for (int nt = 0; nt < 8; nt++)
#pragma unroll
            for (int e = 0; e < 4; e++)
                mx[e >> 1] = fmaxf(mx[e >> 1], sacc[nt][e]);
#pragma unroll
        for (int r = 0; r < 2; r++) {
            mx[r] = fmaxf(mx[r], __shfl_xor_sync(0xffffffffu, mx[r], 1));
            mx[r] = fmaxf(mx[r], __shfl_xor_sync(0xffffffffu, mx[r], 2));
        }
        float corr[2], mnew[2];
#pragma unroll
        for (int r = 0; r < 2; r++) {
            mnew[r] = fmaxf(m_r[r], mx[r]);
            corr[r] = __expf(m_r[r] - mnew[r]);
            m_r[r] = mnew[r];
        }
        float sum[2] = {0.f, 0.f};
#pragma unroll
        for (int nt = 0; nt < 8; nt++)
#pragma unroll
            for (int e = 0; e < 4; e++) {
                float p = __expf(sacc[nt][e] - mnew[e >> 1]);
                sacc[nt][e] = p;
                sum[e >> 1] += p;
            }
#pragma unroll
        for (int r = 0; r < 2; r++) {
            sum[r] += __shfl_xor_sync(0xffffffffu, sum[r], 1);
            sum[r] += __shfl_xor_sync(0xffffffffu, sum[r], 2);
            l_r[r] = l_r[r] * corr[r] + sum[r];
        }
#pragma unroll
        for (int nt = 0; nt < 8; nt++)
#pragma unroll
            for (int e = 0; e < 4; e++) oacc[nt][e] *= corr[e >> 1];

#pragma unroll
        for (int g = 0; g < 4; g++) {
            uint32_t pah[4], pal[4];
            packsplit(sacc[2 * g][0],     sacc[2 * g][1],     pah[0], pal[0]);
            packsplit(sacc[2 * g][2],     sacc[2 * g][3],     pah[1], pal[1]);
            packsplit(sacc[2 * g + 1][0], sacc[2 * g + 1][1], pah[2], pal[2]);
            packsplit(sacc[2 * g + 1][2], sacc[2 * g + 1][3], pah[3], pal[3]);
#pragma unroll
            for (int np = 0; np < 4; np++) {
                uint32_t rh[4], rl[4];
                uint32_t vd = rb + 20480 + (g >> 1) * 5120 + (b_row + np * 16) * 80
                            + (g & 1) * 32 + b_k;
                ldm4(rh, vd);
                ldm4(rl, vd + 10240);
                uint32_t bh0[2] = {rh[0], rh[1]}, bh1[2] = {rh[2], rh[3]};
                uint32_t bl0[2] = {rl[0], rl[1]}, bl1[2] = {rl[2], rl[3]};
                mma_bf16(oacc[2 * np],     pah, bh0);
                mma_bf16(oacc[2 * np],     pah, bl0);
                mma_bf16(oacc[2 * np],     pal, bh0);
                mma_bf16(oacc[2 * np + 1], pah, bh1);
                mma_bf16(oacc[2 * np + 1], pah, bl1);
                mma_bf16(oacc[2 * np + 1], pal, bh1);
            }
        }
        __syncthreads();
    }

#pragma unroll
    for (int r = 0; r < 2; r++) {
        float inv = 1.f / l_r[r];
        int row = q0 + wrow + (lane >> 2) + r * 8;
        long long base = ((long long)(b * 512 + row)) * 512 + h * 64 + (lane & 3) * 2;
#pragma unroll
        for (int nt = 0; nt < 8; nt++) {
            float v0 = oacc[nt][r * 2 + 0] * inv;
            float v1 = oacc[nt][r * 2 + 1] * inv;
            bf16 h0 = __float2bfloat16(v0);
            bf16 h1 = __float2bfloat16(v1);
            uint32_t hi = packbf(h0, h1);
            uint32_t lo = packbf(__float2bfloat16(v0 - __bfloat162float(h0)),
                                 __float2bfloat16(v1 - __bfloat162float(h1)));
            *reinterpret_cast<uint32_t*>(Oh + base + nt * 8) = hi;
            *reinterpret_cast<uint32_t*>(Ol + base + nt * 8) = lo;
        }
    }
}

// ---------------- merged weight transpose+split (3 sources, contiguous out) --
__global__ void k_tsplitw(const float* __restrict__ inA, const float* __restrict__ inB,
                          const float* __restrict__ inC, bf16* __restrict__ oh,
                          bf16* __restrict__ ol, int K, int N, int per)
{
    __shared__ float t[32][33];
    const int z = blockIdx.z;
    const float* in = (z < per) ? inA : ((z < 2 * per) ? inB : inC);
    const int zz = z % per;
    const long long ib = (long long)zz * K * N;
    const long long ob = (long long)z * K * N;
    const int n0 = blockIdx.x * 32, k0 = blockIdx.y * 32;
    const int tx = threadIdx.x, ty = threadIdx.y;

    for (int r = ty; r < 32; r += 8) {
        int k = k0 + r, n = n0 + tx;
        t[r][tx] = (k < K && n < N) ? in[ib + (long long)k * N + n] : 0.f;
    }
    __syncthreads();
    for (int r = ty; r < 32; r += 8) {
        int n = n0 + r, k = k0 + tx;
        if (n < N && k < K) {
            float x = t[tx][r];
            bf16 hi = __float2bfloat16(x);
            oh[ob + (long long)n * K + k] = hi;
            ol[ob + (long long)n * K + k] = __float2bfloat16(x - __bfloat162float(hi));
        }
    }
}

// ---------------- fp16 weight transpose+split (out_w) -------------------------
__global__ void k_tsplitw16(const float* __restrict__ in, f16* __restrict__ oh,
                            f16* __restrict__ ol, int K, int N)
{
    __shared__ float t[32][33];
    const int n0 = blockIdx.x * 32, k0 = blockIdx.y * 32;
    const int tx = threadIdx.x, ty = threadIdx.y;

    for (int r = ty; r < 32; r += 8) {
        int k = k0 + r, n = n0 + tx;
        t[r][tx] = (k < K && n < N) ? in[(long long)k * N + n] : 0.f;
    }
    __syncthreads();
    for (int r = ty; r < 32; r += 8) {
        int n = n0 + r, k = k0 + tx;
        if (n < N && k < K) {
            float x = t[tx][r];
            f16 hi = __float2half(x);
            oh[(long long)n * K + k] = hi;
            ol[(long long)n * K + k] = __float2half(x - __half2float(hi));
        }
    }
}

// ---------------- V^T split from qkv bf16 buffer ------------------------------
__global__ void k_vtsplit(const bf16* __restrict__ ih, const bf16* __restrict__ il,
                          bf16* __restrict__ oh, bf16* __restrict__ ol)
{
    __shared__ float t[32][33];
    const int z = blockIdx.z, b = z >> 3, h = z & 7;
    const int n0 = blockIdx.x * 32, s0 = blockIdx.y * 32;
    const int tx = threadIdx.x, ty = threadIdx.y;
    const long long ib = (long long)b * 512 * 1536 + 1024 + h * 64;
    const long long ob = (long long)z * 64 * 512;

    for (int r = ty; r < 32; r += 8) {
        long long off = ib + (long long)(s0 + r) * 1536 + n0 + tx;
        t[r][tx] = __bfloat162float(ih[off]) + __bfloat162float(il[off]);
    }
    __syncthreads();
    for (int r = ty; r < 32; r += 8) {
        float x = t[tx][r];
        bf16 hi = __float2bfloat16(x);
        long long o = ob + (long long)(n0 + r) * 512 + s0 + tx;
        oh[o] = hi;
        ol[o] = __float2bfloat16(x - __bfloat162float(hi));
    }
}

// ---------------- embedding + posenc (+ split) -------------------------------
__global__ void k_embed(const int* __restrict__ tok, const float* __restrict__ emb,
                        float* __restrict__ out, bf16* __restrict__ oh,
                        bf16* __restrict__ ol)
{
    int idx = blockIdx.x * blockDim.x + threadIdx.x;
    if (idx >= BSc * Dc) return;
    int d  = idx & (Dc - 1);
    int bs = idx >> 9;
    int s  = bs & (Sc - 1);
    int t  = tok[bs];
    int i2 = d & ~1;
    float div = expf((float)i2 * (-9.210340371976184f / (float)Dc));
    float ang = (float)s * div;
    float pe  = (d & 1) ? cosf(ang) : sinf(ang);
    float v = emb[(size_t)t * Dc + d] + pe;
    out[idx] = v;
    bf16 hi = __float2bfloat16(v);
    oh[idx] = hi;
    ol[idx] = __float2bfloat16(v - __bfloat162float(hi));
}

// ---------------- residual + LayerNorm (+ split out) -------------------------
__global__ __launch_bounds__(256) void k_lnres(
    const float* __restrict__ X, const float* __restrict__ Dl,
    const float* __restrict__ g, const float* __restrict__ bt,
    float* __restrict__ Out, bf16* __restrict__ oh, bf16* __restrict__ ol)
{
    int warp = threadIdx.x >> 5, lane = threadIdx.x & 31;
    size_t row = (size_t)blockIdx.x * 8 + warp;
    const float* px = X  + row * Dc;
    const float* pd = Dl + row * Dc;
    float v[16];
    float s = 0.f;
#pragma unroll
    for (int i = 0; i < 16; i++) { v[i] = px[lane + i * 32] + pd[lane + i * 32]; s += v[i]; }
#pragma unroll
    for (int o = 16; o; o >>= 1) s += __shfl_xor_sync(0xffffffffu, s, o);
    float mu = s * (1.f / (float)Dc);
    float var = 0.f;
#pragma unroll
    for (int i = 0; i < 16; i++) { float d = v[i] - mu; var += d * d; }
#pragma unroll
    for (int o = 16; o; o >>= 1) var += __shfl_xor_sync(0xffffffffu, var, o);
    var *= (1.f / (float)Dc);
    float inv = rsqrtf(var + 1e-5f);
#pragma unroll
    for (int i = 0; i < 16; i++) {
        int c = lane + i * 32;
        float o = (v[i] - mu) * inv * g[c] + bt[c];
        Out[row * Dc + c] = o;
        bf16 hi = __float2bfloat16(o);
        oh[row * Dc + c] = hi;
        ol[row * Dc + c] = __float2bfloat16(o - __bfloat162float(hi));
    }
}

// ---------------- residual + LayerNorm (fp16 single out, final decoder) ------
__global__ __launch_bounds__(256) void k_lnres16(
    const float* __restrict__ X, const float* __restrict__ Dl,
    const float* __restrict__ g, const float* __restrict__ bt,
    float* __restrict__ Out, f16* __restrict__ o16)
{
    int warp = threadIdx.x >> 5, lane = threadIdx.x & 31;
    size_t row = (size_t)blockIdx.x * 8 + warp;
    const float* px = X  + row * Dc;
    const float* pd = Dl + row * Dc;
    float v[16];
    float s = 0.f;
#pragma unroll
    for (int i = 0; i < 16; i++) { v[i] = px[lane + i * 32] + pd[lane + i * 32]; s += v[i]; }
#pragma unroll
    for (int o = 16; o; o >>= 1) s += __shfl_xor_sync(0xffffffffu, s, o);
    float mu = s * (1.f / (float)Dc);
    float var = 0.f;
#pragma unroll
    for (int i = 0; i < 16; i++) { float d = v[i] - mu; var += d * d; }
#pragma unroll
    for (int o = 16; o; o >>= 1) var += __shfl_xor_sync(0xffffffffu, var, o);
    var *= (1.f / (float)Dc);
    float inv = rsqrtf(var + 1e-5f);
#pragma unroll
    for (int i = 0; i < 16; i++) {
        int c = lane + i * 32;
        float o = (v[i] - mu) * inv * g[c] + bt[c];
        Out[row * Dc + c] = o;
        o16[row * Dc + c] = __float2half(o);
    }
}

// =============================================================================
extern "C" void kernel_launch(void* const* d_in, const int* in_sizes, int n_in,
                              void* d_out, int out_size)
{
    const int*   src      = (const int*)  d_in[0];
    const int*   tgt      = (const int*)  d_in[1];
    const float* src_emb  = (const float*)d_in[2];
    const float* tgt_emb  = (const float*)d_in[3];
    const float* e_qkvo_w = (const float*)d_in[4];
    const float* e_qkvo_b = (const float*)d_in[5];
    const float* e_ff1_w  = (const float*)d_in[6];
    const float* e_ff1_b  = (const float*)d_in[7];
    const float* e_ff2_w  = (const float*)d_in[8];
    const float* e_ff2_b  = (const float*)d_in[9];
    const float* e_ln_g   = (const float*)d_in[10];
    const float* e_ln_b   = (const float*)d_in[11];
    const float* d_sa_w   = (const float*)d_in[12];
    const float* d_sa_b   = (const float*)d_in[13];
    const float* d_ca_w   = (const float*)d_in[14];
    const float* d_ca_b   = (const float*)d_in[15];
    const float* d_ff1_w  = (const float*)d_in[16];
    const float* d_ff1_b  = (const float*)d_in[17];
    const float* d_ff2_w  = (const float*)d_in[18];
    const float* d_ff2_b  = (const float*)d_in[19];
    const float* d_ln_g   = (const float*)d_in[20];
    const float* d_ln_b   = (const float*)d_in[21];
    const float* out_w    = (const float*)d_in[22];
    const float* out_b    = (const float*)d_in[23];
    float* out = (float*)d_out;

    float *px, *py, *pa;
    bf16 *wh, *wl, *qvh, *qvl, *ah, *al, *dyh, *dyl, *fh, *fl, *vth, *vtl,
         *th, *tl, *xeh, *xel;
    f16 *owh, *owl, *a16;
    cudaGetSymbolAddress((void**)&px,  g_x);
    cudaGetSymbolAddress((void**)&py,  g_y);
    cudaGetSymbolAddress((void**)&pa,  g_a);
    cudaGetSymbolAddress((void**)&wh,  g_wh);
    cudaGetSymbolAddress((void**)&wl,  g_wl);
    cudaGetSymbolAddress((void**)&qvh, g_qkvh);
    cudaGetSymbolAddress((void**)&qvl, g_qkvl);
    cudaGetSymbolAddress((void**)&ah,  g_ah);
    cudaGetSymbolAddress((void**)&al,  g_al);
    cudaGetSymbolAddress((void**)&dyh, g_dyh);
    cudaGetSymbolAddress((void**)&dyl, g_dyl);
    cudaGetSymbolAddress((void**)&fh,  g_fh);
    cudaGetSymbolAddress((void**)&fl,  g_fl);
    cudaGetSymbolAddress((void**)&vth, g_vth);
    cudaGetSymbolAddress((void**)&vtl, g_vtl);
    cudaGetSymbolAddress((void**)&th,  g_th);
    cudaGetSymbolAddress((void**)&tl,  g_tl);
    cudaGetSymbolAddress((void**)&xeh, g_xeh);
    cudaGetSymbolAddress((void**)&xel, g_xel);
    cudaGetSymbolAddress((void**)&owh, g_owh);
    cudaGetSymbolAddress((void**)&owl, g_owl);
    cudaGetSymbolAddress((void**)&a16, g_a16);

    const int SMEM64  = 3 * (2 * 128 * 80 + 2 * 64 * 80);  // 92160 -> 2 CTAs/SM
    const int SMEMH   = 3 * (128 * 80 + 2 * 64 * 80);      // 61440
    const int FLASH_SMEM = 104448;
    cudaFuncSetAttribute((const void*)k_tgemm<64>,
                         cudaFuncAttributeMaxDynamicSharedMemorySize, SMEM64);
    cudaFuncSetAttribute((const void*)k_hgemm,
                         cudaFuncAttributeMaxDynamicSharedMemorySize, SMEMH);
    cudaFuncSetAttribute((const void*)k_flash,
                         cudaFuncAttributeMaxDynamicSharedMemorySize, FLASH_SMEM);

    // ---- launchers ----------------------------------------------------------
    auto dense = [&](const bf16* Axh, const bf16* Axl, int lda, long long woff,
                     int ldb, float* C, bf16* Oh, bf16* Ol, int ldc,
                     const float* bias, int relu, int N, int K) {
        dim3 g((N + 63) / 64, BSc / 128, 1);
        k_tgemm<64><<<g, 256, SMEM64>>>(Axh, Axl, lda, 0, 0,
                                        wh + woff, wl + woff, ldb, 0, 0,
                                        C, Oh, Ol, ldc, 0, 0,
                                        bias, relu, N, K, 1.f);
    };
    auto flash = [&](int causal, const int* kt) {
        k_flash<<<dim3(4, 64), 256, FLASH_SMEM>>>(qvh, qvl, qvh + 512, qvl + 512,
                                                  vth, vtl, th, tl, kt, causal);
    };
    auto vtsplit = [&]() {
        k_vtsplit<<<dim3(2, 16, 64), dim3(32, 8)>>>(qvh, qvl, vth, vtl);
    };
    const int ln_blocks = BSc / 8;
    const long long DD = (long long)Dc * Dc;

    // ---- prologue (launch #4 = dense GEMM, captured by ncu) ------------------
    k_tsplitw<<<dim3(16, 16, 72), dim3(32, 8)>>>(e_qkvo_w, d_sa_w, d_ca_w,
                                                 wh, wl, 512, 512, 24);
    k_embed<<<(BSc * Dc + 255) / 256, 256>>>(src, src_emb, px, ah, al);
    k_tsplitw<<<dim3(64, 16, 12), dim3(32, 8)>>>(e_ff1_w, d_ff1_w, d_ff1_w,
                                                 wh + OFF_FF1E, wl + OFF_FF1E,
                                                 512, 2048, 6);
    dense(ah, al, Dc, OFF_QKVO_E, Dc, nullptr, qvh, qvl, 1536, e_qkvo_b, 0, 1536, Dc);
    k_tsplitw<<<dim3(16, 64, 12), dim3(32, 8)>>>(e_ff2_w, d_ff2_w, d_ff2_w,
                                                 wh + OFF_FF2E, wl + OFF_FF2E,
                                                 2048, 512, 6);
    k_tsplitw16<<<dim3(313, 16), dim3(32, 8)>>>(out_w, owh, owl, 512, 10000);
    k_embed<<<(BSc * Dc + 255) / 256, 256>>>(tgt, tgt_emb, py, dyh, dyl);

    // ================= encoder =================
    for (int l = 0; l < Lc; l++) {
        long long w = OFF_QKVO_E + (long long)l * 4 * DD;
        const float* b = e_qkvo_b + (size_t)l * 4 * Dc;
        if (l > 0)
            dense(ah, al, Dc, w, Dc, nullptr, qvh, qvl, 1536, b, 0, 1536, Dc);
        vtsplit();
        flash(0, src);
        dense(th, tl, Dc, w + 3 * DD, Dc, pa, nullptr, nullptr, Dc, b + 3 * Dc, 0, Dc, Dc);
        k_lnres<<<ln_blocks, 256>>>(px, pa, e_ln_g + (size_t)l * 2 * Dc,
                                    e_ln_b + (size_t)l * 2 * Dc, px, ah, al);
        dense(ah, al, Dc, OFF_FF1E + (long long)l * Dc * FFc, Dc,
              nullptr, fh, fl, FFc, e_ff1_b + (size_t)l * FFc, 1, FFc, Dc);
        dense(fh, fl, FFc, OFF_FF2E + (long long)l * Dc * FFc, FFc,
              pa, nullptr, nullptr, Dc, e_ff2_b + (size_t)l * Dc, 0, Dc, FFc);
        bf16* oh2 = (l == Lc - 1) ? xeh : ah;
        bf16* ol2 = (l == Lc - 1) ? xel : al;
        k_lnres<<<ln_blocks, 256>>>(px, pa, e_ln_g + (size_t)l * 2 * Dc + Dc,
                                    e_ln_b + (size_t)l * 2 * Dc + Dc, px, oh2, ol2);
    }

    // ================= decoder =================
    for (int l = 0; l < Lc; l++) {
        long long ws = OFF_SA + (long long)l * 4 * DD;
        const float* bs = d_sa_b + (size_t)l * 4 * Dc;
        const bf16* ain_h = (l == 0) ? dyh : ah;
        const bf16* ain_l = (l == 0) ? dyl : al;
        dense(ain_h, ain_l, Dc, ws, Dc, nullptr, qvh, qvl, 1536, bs, 0, 1536, Dc);
        vtsplit();
        flash(1, nullptr);
        dense(th, tl, Dc, ws + 3 * DD, Dc, pa, nullptr, nullptr, Dc, bs + 3 * Dc, 0, Dc, Dc);
        k_lnres<<<ln_blocks, 256>>>(py, pa, d_ln_g + (size_t)l * 3 * Dc,
                                    d_ln_b + (size_t)l * 3 * Dc, py, ah, al);

        long long wc = OFF_CA + (long long)l * 4 * DD;
        const float* bc = d_ca_b + (size_t)l * 4 * Dc;
        dense(ah,  al,  Dc, wc,      Dc, nullptr, qvh, qvl, 1536, bc, 0, Dc, Dc);
        dense(xeh, xel, Dc, wc + DD, Dc, nullptr, qvh + 512, qvl + 512, 1536,
              bc + Dc, 0, 1024, Dc);
        vtsplit();
        flash(0, tgt);
        dense(th, tl, Dc, wc + 3 * DD, Dc, pa, nullptr, nullptr, Dc, bc + 3 * Dc, 0, Dc, Dc);
        k_lnres<<<ln_blocks, 256>>>(py, pa, d_ln_g + (size_t)l * 3 * Dc + Dc,
                                    d_ln_b + (size_t)l * 3 * Dc + Dc, py, ah, al);

        dense(ah, al, Dc, OFF_FF1D + (long long)l * Dc * FFc, Dc,
              nullptr, fh, fl, FFc, d_ff1_b + (size_t)l * FFc, 1, FFc, Dc);
        dense(fh, fl, FFc, OFF_FF2D + (long long)l * Dc * FFc, FFc,
              pa, nullptr, nullptr, Dc, d_ff2_b + (size_t)l * Dc, 0, Dc, FFc);
        if (l == Lc - 1)
            k_lnres16<<<ln_blocks, 256>>>(py, pa, d_ln_g + (size_t)l * 3 * Dc + 2 * Dc,
                                          d_ln_b + (size_t)l * 3 * Dc + 2 * Dc, py, a16);
        else
            k_lnres<<<ln_blocks, 256>>>(py, pa, d_ln_g + (size_t)l * 3 * Dc + 2 * Dc,
                                        d_ln_b + (size_t)l * 3 * Dc + 2 * Dc, py, ah, al);
    }

    // ================= output projection (fp16 2-term) ========================
    k_hgemm<<<dim3((Vc + 63) / 64, BSc / 128), 256, SMEMH>>>(
        a16, Dc, owh, owl, Dc, out, out_b, Vc, Dc);
}